// round 1
// baseline (speedup 1.0000x reference)
#include <cuda_runtime.h>
#include <math.h>

// ---------------- problem constants ----------------
#define B_   2
#define T_   1024
#define E_   1024
#define H_   16
#define HD_  64
#define L_   8
#define FF_  4096
#define V_   32000
#define BT_  (B_ * T_)
#define EPS_ 1e-5f
#define SCALE_ 0.03125f   // 1/sqrt(E)

// ---------------- scratch (device globals; no allocation allowed) ----------------
__device__ float g_x[BT_ * E_];
__device__ float g_h[BT_ * E_];
__device__ float g_q[BT_ * E_];
__device__ float g_k[BT_ * E_];
__device__ float g_v[BT_ * E_];
__device__ float g_o[BT_ * E_];
__device__ float g_ff[(size_t)BT_ * FF_];
__device__ float g_scores[(size_t)B_ * H_ * T_ * T_];
__device__ float g_logits[(size_t)BT_ * V_];
__device__ float g_rowloss[BT_];
__device__ float g_lossdummy[4];

// ---------------- reductions (blockDim.x == 256) ----------------
__device__ __forceinline__ float blockSum256(float v) {
    __shared__ float sh[8];
    int tid = threadIdx.x;
    #pragma unroll
    for (int o = 16; o; o >>= 1) v += __shfl_xor_sync(0xffffffffu, v, o);
    __syncthreads();
    if ((tid & 31) == 0) sh[tid >> 5] = v;
    __syncthreads();
    v = sh[tid & 7];
    #pragma unroll
    for (int o = 4; o; o >>= 1) v += __shfl_xor_sync(0xffffffffu, v, o);
    return v;
}

__device__ __forceinline__ float blockMax256(float v) {
    __shared__ float sh[8];
    int tid = threadIdx.x;
    #pragma unroll
    for (int o = 16; o; o >>= 1) v = fmaxf(v, __shfl_xor_sync(0xffffffffu, v, o));
    __syncthreads();
    if ((tid & 31) == 0) sh[tid >> 5] = v;
    __syncthreads();
    v = sh[tid & 7];
    #pragma unroll
    for (int o = 4; o; o >>= 1) v = fmaxf(v, __shfl_xor_sync(0xffffffffu, v, o));
    return v;
}

// ---------------- embedding ----------------
__global__ void embed_kernel(const int* __restrict__ ctx,
                             const float* __restrict__ tok,
                             const float* __restrict__ pos) {
    int gid = blockIdx.x * blockDim.x + threadIdx.x;   // BT_*E_ threads
    int bt = gid >> 10;          // / E_
    int e  = gid & (E_ - 1);
    int t  = bt & (T_ - 1);
    g_x[gid] = tok[(size_t)ctx[bt] * E_ + e] + pos[t * E_ + e];
}

// ---------------- layernorm (one block per row, 256 threads, float4) ----------------
__global__ void ln_kernel(const float* __restrict__ in, float* __restrict__ out,
                          const float* __restrict__ g, const float* __restrict__ b) {
    int row = blockIdx.x;
    int tid = threadIdx.x;
    const float4* rp = (const float4*)(in + (size_t)row * E_);
    float4 v = rp[tid];
    float s  = v.x + v.y + v.z + v.w;
    float ss = v.x * v.x + v.y * v.y + v.z * v.z + v.w * v.w;
    s  = blockSum256(s);
    __syncthreads();
    ss = blockSum256(ss);
    float mean = s * (1.0f / E_);
    float var  = ss * (1.0f / E_) - mean * mean;
    float inv  = rsqrtf(var + EPS_);
    int e = tid * 4;
    float4 o;
    o.x = (v.x - mean) * inv * g[e + 0] + b[e + 0];
    o.y = (v.y - mean) * inv * g[e + 1] + b[e + 1];
    o.z = (v.z - mean) * inv * g[e + 2] + b[e + 2];
    o.w = (v.w - mean) * inv * g[e + 3] + b[e + 3];
    ((float4*)(out + (size_t)row * E_))[tid] = o;
}

// ---------------- generic SGEMM NN: C = A@B (+bias +residual, optional relu) -------
// 64x64 tile, BK=16, 256 threads, 4x4 per thread. All dims multiples of 64/16.
__global__ void sgemm_nn(const float* __restrict__ A, const float* __restrict__ Bm,
                         const float* __restrict__ bias, const float* __restrict__ res,
                         float* __restrict__ C, int M, int N, int K,
                         int lda, int ldb, int ldc, int doRelu) {
    __shared__ float As[16][65];
    __shared__ float Bs[16][64];
    int tid = threadIdx.x;
    int tx = tid & 15, ty = tid >> 4;
    int row0 = blockIdx.y * 64, col0 = blockIdx.x * 64;
    int lm = tid >> 2;            // 0..63 (A row)
    int lk = (tid & 3) * 4;       // 0,4,8,12 (A k)
    int bk = tid >> 4;            // 0..15 (B k)
    int bn = (tid & 15) * 4;      // B col
    const float* Ab = A + (size_t)row0 * lda;
    const float* Bb = Bm + col0;
    float acc[4][4] = {};
    for (int k0 = 0; k0 < K; k0 += 16) {
        float4 av = *(const float4*)(Ab + (size_t)lm * lda + k0 + lk);
        As[lk + 0][lm] = av.x; As[lk + 1][lm] = av.y;
        As[lk + 2][lm] = av.z; As[lk + 3][lm] = av.w;
        *(float4*)&Bs[bk][bn] = *(const float4*)(Bb + (size_t)(k0 + bk) * ldb + bn);
        __syncthreads();
        #pragma unroll
        for (int kk = 0; kk < 16; kk++) {
            float a[4], bb[4];
            #pragma unroll
            for (int i = 0; i < 4; i++) a[i] = As[kk][ty * 4 + i];
            #pragma unroll
            for (int j = 0; j < 4; j++) bb[j] = Bs[kk][tx * 4 + j];
            #pragma unroll
            for (int i = 0; i < 4; i++)
                #pragma unroll
                for (int j = 0; j < 4; j++)
                    acc[i][j] += a[i] * bb[j];
        }
        __syncthreads();
    }
    #pragma unroll
    for (int i = 0; i < 4; i++) {
        int r = row0 + ty * 4 + i;
        #pragma unroll
        for (int j = 0; j < 4; j++) {
            int c = col0 + tx * 4 + j;
            float v = acc[i][j];
            if (bias) v += bias[c];
            if (res)  v += res[(size_t)r * ldc + c];
            if (doRelu) v = fmaxf(v, 0.0f);
            C[(size_t)r * ldc + c] = v;
        }
    }
}

// ---------------- attention: scores = scale * Q @ K^T (per b,h), causal-tile skip --
__global__ void attn_scores_kernel(const float* __restrict__ q, const float* __restrict__ k) {
    int z = blockIdx.z;  int b = z >> 4;  int h = z & 15;
    int qt = blockIdx.y, kt = blockIdx.x;
    if (kt > qt) return;                 // fully above diagonal: skip
    const float* A  = q + (size_t)b * T_ * E_ + h * HD_;
    const float* Bm = k + (size_t)b * T_ * E_ + h * HD_;
    float* C = g_scores + (size_t)z * T_ * T_;
    int row0 = qt * 64, col0 = kt * 64;
    __shared__ float As[16][65];
    __shared__ float Bs[16][65];
    int tid = threadIdx.x;
    int tx = tid & 15, ty = tid >> 4;
    int lm = tid >> 2;
    int lk = (tid & 3) * 4;
    float acc[4][4] = {};
    #pragma unroll
    for (int k0 = 0; k0 < HD_; k0 += 16) {
        float4 av = *(const float4*)(A + (size_t)(row0 + lm) * E_ + k0 + lk);
        As[lk + 0][lm] = av.x; As[lk + 1][lm] = av.y;
        As[lk + 2][lm] = av.z; As[lk + 3][lm] = av.w;
        float4 bv = *(const float4*)(Bm + (size_t)(col0 + lm) * E_ + k0 + lk);
        Bs[lk + 0][lm] = bv.x; Bs[lk + 1][lm] = bv.y;
        Bs[lk + 2][lm] = bv.z; Bs[lk + 3][lm] = bv.w;
        __syncthreads();
        #pragma unroll
        for (int kk = 0; kk < 16; kk++) {
            float a[4], bb[4];
            #pragma unroll
            for (int i = 0; i < 4; i++) a[i] = As[kk][ty * 4 + i];
            #pragma unroll
            for (int j = 0; j < 4; j++) bb[j] = Bs[kk][tx * 4 + j];
            #pragma unroll
            for (int i = 0; i < 4; i++)
                #pragma unroll
                for (int j = 0; j < 4; j++)
                    acc[i][j] += a[i] * bb[j];
        }
        __syncthreads();
    }
    #pragma unroll
    for (int i = 0; i < 4; i++)
        #pragma unroll
        for (int j = 0; j < 4; j++)
            C[(size_t)(row0 + ty * 4 + i) * T_ + col0 + tx * 4 + j] = acc[i][j] * SCALE_;
}

// ---------------- causal row softmax (one block per (b,h,q) row) -------------------
__global__ void softmax_kernel() {
    int idx = blockIdx.x;                 // b*H*T + h*T + q
    int q = idx & (T_ - 1);
    float* row = g_scores + (size_t)idx * T_;
    int n = q + 1;
    int tid = threadIdx.x;
    float m = -1e30f;
    for (int i = tid; i < n; i += 256) m = fmaxf(m, row[i]);
    m = blockMax256(m);
    __syncthreads();
    float s = 0.0f;
    for (int i = tid; i < n; i += 256) {
        float e = expf(row[i] - m);
        row[i] = e;
        s += e;
    }
    s = blockSum256(s);
    float inv = 1.0f / s;
    for (int i = tid; i < n; i += 256) row[i] *= inv;
    for (int i = n + tid; i < T_; i += 256) row[i] = 0.0f;   // zero masked tail
}

// ---------------- O = attn @ V (per b,h); K loop bounded by causal tile ------------
__global__ void attn_av_kernel(const float* __restrict__ v) {
    int z = blockIdx.z;  int b = z >> 4;  int h = z & 15;
    int qt = blockIdx.y;
    const float* A  = g_scores + (size_t)z * T_ * T_;
    const float* Bm = v + (size_t)b * T_ * E_ + h * HD_;
    float* C = g_o + (size_t)b * T_ * E_ + h * HD_;
    int row0 = qt * 64;
    int Kmax = row0 + 64;                 // keys beyond tile's max q are zero
    __shared__ float As[16][65];
    __shared__ float Bs[16][64];
    int tid = threadIdx.x;
    int tx = tid & 15, ty = tid >> 4;
    int lm = tid >> 2;
    int lk = (tid & 3) * 4;
    int bk = tid >> 4;
    int bn = (tid & 15) * 4;
    float acc[4][4] = {};
    for (int k0 = 0; k0 < Kmax; k0 += 16) {
        float4 av = *(const float4*)(A + (size_t)(row0 + lm) * T_ + k0 + lk);
        As[lk + 0][lm] = av.x; As[lk + 1][lm] = av.y;
        As[lk + 2][lm] = av.z; As[lk + 3][lm] = av.w;
        *(float4*)&Bs[bk][bn] = *(const float4*)(Bm + (size_t)(k0 + bk) * E_ + bn);
        __syncthreads();
        #pragma unroll
        for (int kk = 0; kk < 16; kk++) {
            float a[4], bb[4];
            #pragma unroll
            for (int i = 0; i < 4; i++) a[i] = As[kk][ty * 4 + i];
            #pragma unroll
            for (int j = 0; j < 4; j++) bb[j] = Bs[kk][tx * 4 + j];
            #pragma unroll
            for (int i = 0; i < 4; i++)
                #pragma unroll
                for (int j = 0; j < 4; j++)
                    acc[i][j] += a[i] * bb[j];
        }
        __syncthreads();
    }
    #pragma unroll
    for (int i = 0; i < 4; i++)
        #pragma unroll
        for (int j = 0; j < 4; j++)
            C[(size_t)(row0 + ty * 4 + i) * E_ + tx * 4 + j] = acc[i][j];
}

// ---------------- loss: per-row log-softmax NLL, then deterministic mean ------------
__global__ void rowloss_kernel(const float* __restrict__ logits, const int* __restrict__ tgt) {
    int row = blockIdx.x;
    const float* lr = logits + (size_t)row * V_;
    int tid = threadIdx.x;
    float m = -1e30f;
    for (int i = tid; i < V_; i += 256) m = fmaxf(m, lr[i]);
    m = blockMax256(m);
    __syncthreads();
    float s = 0.0f;
    for (int i = tid; i < V_; i += 256) s += expf(lr[i] - m);
    s = blockSum256(s);
    if (tid == 0)
        g_rowloss[row] = -(lr[tgt[row]] - m - logf(s));
}

__global__ void loss_final_kernel(float* __restrict__ dst) {
    int tid = threadIdx.x;
    float s = 0.0f;
    for (int i = tid; i < BT_; i += 256) s += g_rowloss[i];
    s = blockSum256(s);
    if (tid == 0) dst[0] = s * (1.0f / BT_);
}

// ---------------- host driver ----------------
extern "C" void kernel_launch(void* const* d_in, const int* in_sizes, int n_in,
                              void* d_out, int out_size) {
    const int*   context = (const int*)  d_in[0];
    const int*   targets = (const int*)  d_in[1];
    const float* tok_emb = (const float*)d_in[2];
    const float* pos_emb = (const float*)d_in[3];
    const float* Wq    = (const float*)d_in[4];
    const float* Wk    = (const float*)d_in[5];
    const float* Wv    = (const float*)d_in[6];
    const float* Wo    = (const float*)d_in[7];
    const float* bo    = (const float*)d_in[8];
    const float* ln1_g = (const float*)d_in[9];
    const float* ln1_b = (const float*)d_in[10];
    const float* ln2_g = (const float*)d_in[11];
    const float* ln2_b = (const float*)d_in[12];
    const float* W1    = (const float*)d_in[13];
    const float* b1    = (const float*)d_in[14];
    const float* W2    = (const float*)d_in[15];
    const float* b2    = (const float*)d_in[16];
    const float* lnf_g = (const float*)d_in[17];
    const float* lnf_b = (const float*)d_in[18];
    const float* Wlm   = (const float*)d_in[19];
    const float* blm   = (const float*)d_in[20];

    float *x, *h, *q, *k, *v, *o, *ff, *logits_sym, *lossdummy;
    cudaGetSymbolAddress((void**)&x,  g_x);
    cudaGetSymbolAddress((void**)&h,  g_h);
    cudaGetSymbolAddress((void**)&q,  g_q);
    cudaGetSymbolAddress((void**)&k,  g_k);
    cudaGetSymbolAddress((void**)&v,  g_v);
    cudaGetSymbolAddress((void**)&o,  g_o);
    cudaGetSymbolAddress((void**)&ff, g_ff);
    cudaGetSymbolAddress((void**)&logits_sym, g_logits);
    cudaGetSymbolAddress((void**)&lossdummy,  g_lossdummy);

    const long long BTV = (long long)BT_ * V_;
    float* out = (float*)d_out;
    float* logits = ((long long)out_size >= BTV) ? out : logits_sym;
    float* lossdst;
    if ((long long)out_size > BTV)       lossdst = out + BTV;   // logits + loss
    else if ((long long)out_size < BTV)  lossdst = out;         // loss only
    else                                 lossdst = lossdummy;   // logits only

    // embedding
    embed_kernel<<<(BT_ * E_) / 256, 256>>>(context, tok_emb, pos_emb);

    dim3 gE(E_ / 64, BT_ / 64);     // 2048 x 1024 gemm grid
    dim3 gFF(FF_ / 64, BT_ / 64);
    dim3 gV(V_ / 64, BT_ / 64);
    dim3 gS(T_ / 64, T_ / 64, B_ * H_);
    dim3 gAV(1, T_ / 64, B_ * H_);

    for (int l = 0; l < L_; l++) {
        const float* wq = Wq + (size_t)l * E_ * E_;
        const float* wk = Wk + (size_t)l * E_ * E_;
        const float* wv = Wv + (size_t)l * E_ * E_;
        const float* wo = Wo + (size_t)l * E_ * E_;
        const float* w1 = W1 + (size_t)l * E_ * FF_;
        const float* w2 = W2 + (size_t)l * FF_ * E_;

        // h = ln1(x)
        ln_kernel<<<BT_, 256>>>(x, h, ln1_g + l * E_, ln1_b + l * E_);
        // q,k,v
        sgemm_nn<<<gE, 256>>>(h, wq, nullptr, nullptr, q, BT_, E_, E_, E_, E_, E_, 0);
        sgemm_nn<<<gE, 256>>>(h, wk, nullptr, nullptr, k, BT_, E_, E_, E_, E_, E_, 0);
        sgemm_nn<<<gE, 256>>>(h, wv, nullptr, nullptr, v, BT_, E_, E_, E_, E_, E_, 0);
        // attention
        attn_scores_kernel<<<gS, 256>>>(q, k);
        softmax_kernel<<<B_ * H_ * T_, 256>>>();
        attn_av_kernel<<<gAV, 256>>>(v);
        // x = x + o @ Wo + bo  (in-place residual)
        sgemm_nn<<<gE, 256>>>(o, wo, bo + l * E_, x, x, BT_, E_, E_, E_, E_, E_, 0);
        // h = ln2(x)
        ln_kernel<<<BT_, 256>>>(x, h, ln2_g + l * E_, ln2_b + l * E_);
        // ff = relu(h @ W1 + b1)
        sgemm_nn<<<gFF, 256>>>(h, w1, b1 + l * FF_, nullptr, ff, BT_, FF_, E_, E_, FF_, FF_, 1);
        // x = x + ff @ W2 + b2
        sgemm_nn<<<gE, 256>>>(ff, w2, b2 + l * E_, x, x, BT_, E_, FF_, FF_, E_, E_, 0);
    }

    // final layernorm + LM head
    ln_kernel<<<BT_, 256>>>(x, h, lnf_g, lnf_b);
    sgemm_nn<<<gV, 256>>>(h, Wlm, blm, nullptr, logits, BT_, V_, E_, E_, V_, V_, 0);

    // loss
    rowloss_kernel<<<BT_, 256>>>(logits, targets);
    loss_final_kernel<<<1, 256>>>(lossdst);
}

// round 4
// speedup vs baseline: 1.3720x; 1.3720x over previous
#include <cuda_runtime.h>
#include <cuda_bf16.h>
#include <stdint.h>
#include <math.h>

// ---------------- problem constants ----------------
#define B_   2
#define T_   1024
#define E_   1024
#define H_   16
#define HD_  64
#define L_   8
#define FF_  4096
#define V_   32000
#define BT_  (B_ * T_)
#define EPS_ 1e-5f
#define SCALE_ 0.03125f   // 1/sqrt(E)

// ---------------- scratch (device globals; no allocation allowed) ----------------
__device__ float g_x[BT_ * E_];
__device__ float g_h[BT_ * E_];
__device__ float g_q[BT_ * E_];
__device__ float g_k[BT_ * E_];
__device__ float g_v[BT_ * E_];
__device__ float g_o[BT_ * E_];
__device__ float g_ff[(size_t)BT_ * FF_];
__device__ float g_scores[(size_t)B_ * H_ * T_ * T_];
__device__ float g_logits[(size_t)BT_ * V_];
__device__ float g_rowloss[BT_];
__device__ float g_lossdummy[4];

// ---------------- reductions (blockDim.x == 256) ----------------
__device__ __forceinline__ float blockSum256(float v) {
    __shared__ float sh[8];
    int tid = threadIdx.x;
    #pragma unroll
    for (int o = 16; o; o >>= 1) v += __shfl_xor_sync(0xffffffffu, v, o);
    __syncthreads();
    if ((tid & 31) == 0) sh[tid >> 5] = v;
    __syncthreads();
    v = sh[tid & 7];
    #pragma unroll
    for (int o = 4; o; o >>= 1) v += __shfl_xor_sync(0xffffffffu, v, o);
    return v;
}

__device__ __forceinline__ float blockMax256(float v) {
    __shared__ float sh[8];
    int tid = threadIdx.x;
    #pragma unroll
    for (int o = 16; o; o >>= 1) v = fmaxf(v, __shfl_xor_sync(0xffffffffu, v, o));
    __syncthreads();
    if ((tid & 31) == 0) sh[tid >> 5] = v;
    __syncthreads();
    v = sh[tid & 7];
    #pragma unroll
    for (int o = 4; o; o >>= 1) v = fmaxf(v, __shfl_xor_sync(0xffffffffu, v, o));
    return v;
}

// ---------------- embedding ----------------
__global__ void embed_kernel(const int* __restrict__ ctx,
                             const float* __restrict__ tok,
                             const float* __restrict__ pos) {
    int gid = blockIdx.x * blockDim.x + threadIdx.x;
    int bt = gid >> 10;
    int e  = gid & (E_ - 1);
    int t  = bt & (T_ - 1);
    g_x[gid] = tok[(size_t)ctx[bt] * E_ + e] + pos[t * E_ + e];
}

// ---------------- layernorm ----------------
__global__ void ln_kernel(const float* __restrict__ in, float* __restrict__ out,
                          const float* __restrict__ g, const float* __restrict__ b) {
    int row = blockIdx.x;
    int tid = threadIdx.x;
    const float4* rp = (const float4*)(in + (size_t)row * E_);
    float4 v = rp[tid];
    float s  = v.x + v.y + v.z + v.w;
    float ss = v.x * v.x + v.y * v.y + v.z * v.z + v.w * v.w;
    s  = blockSum256(s);
    __syncthreads();
    ss = blockSum256(ss);
    float mean = s * (1.0f / E_);
    float var  = ss * (1.0f / E_) - mean * mean;
    float inv  = rsqrtf(var + EPS_);
    int e = tid * 4;
    float4 o;
    o.x = (v.x - mean) * inv * g[e + 0] + b[e + 0];
    o.y = (v.y - mean) * inv * g[e + 1] + b[e + 1];
    o.z = (v.z - mean) * inv * g[e + 2] + b[e + 2];
    o.w = (v.w - mean) * inv * g[e + 3] + b[e + 3];
    ((float4*)(out + (size_t)row * E_))[tid] = o;
}

// ============ bf16x3 split tensor-core GEMM ============
// C = A(MxK) @ B(KxN) (+bias +res, optional relu), A/B/C fp32 row-major.
// Each fp32 x is split as x = hi + lo (bf16 each); acc += Ahi*Bhi + Ahi*Blo + Alo*Bhi.
// Block tile 128x128, BK=32, 256 threads (8 warps, each 32x64).
#define MMA16816(c, a, b) \
  asm volatile("mma.sync.aligned.m16n8k16.row.col.f32.bf16.bf16.f32 " \
    "{%0,%1,%2,%3}, {%4,%5,%6,%7}, {%8,%9}, {%0,%1,%2,%3};" \
    : "+f"((c)[0]), "+f"((c)[1]), "+f"((c)[2]), "+f"((c)[3]) \
    : "r"((a)[0]), "r"((a)[1]), "r"((a)[2]), "r"((a)[3]), \
      "r"((b)[0]), "r"((b)[1]))

__global__ void __launch_bounds__(256) mma_gemm(
        const float* __restrict__ A, const float* __restrict__ Bm,
        const float* __restrict__ bias, const float* __restrict__ res,
        float* __restrict__ C, int M, int N, int K,
        int lda, int ldb, int ldc, int doRelu) {
    // [hi/lo][row][k], k-contiguous, padded to 36 halves (72B rows)
    __shared__ __nv_bfloat16 sA[2][128][36];
    __shared__ __nv_bfloat16 sB[2][128][36];

    int tid  = threadIdx.x;
    int warp = tid >> 5, lane = tid & 31;
    int wm = warp & 3;          // 0..3  -> M offset wm*32
    int wn = warp >> 2;         // 0..1  -> N offset wn*64
    int g  = lane >> 2;         // 0..7
    int tg = lane & 3;          // 0..3

    int row0 = blockIdx.y * 128;
    int col0 = blockIdx.x * 128;

    float acc[2][8][4];
    #pragma unroll
    for (int i = 0; i < 2; i++)
        #pragma unroll
        for (int j = 0; j < 8; j++)
            #pragma unroll
            for (int r = 0; r < 4; r++) acc[i][j][r] = 0.0f;

    for (int k0 = 0; k0 < K; k0 += 32) {
        // ---- load A tile 128x32 (fp32 -> split bf16) ----
        #pragma unroll
        for (int i = 0; i < 4; i++) {
            int idx = i * 256 + tid;
            int m  = idx >> 3;
            int kq = (idx & 7) * 4;
            float4 av = *(const float4*)(A + (size_t)(row0 + m) * lda + k0 + kq);
            float vv[4] = {av.x, av.y, av.z, av.w};
            #pragma unroll
            for (int j = 0; j < 4; j++) {
                __nv_bfloat16 hi = __float2bfloat16(vv[j]);
                __nv_bfloat16 lo = __float2bfloat16(vv[j] - __bfloat162float(hi));
                sA[0][m][kq + j] = hi;
                sA[1][m][kq + j] = lo;
            }
        }
        // ---- load B tile 32x128, transposed into sB[n][k] ----
        #pragma unroll
        for (int i = 0; i < 4; i++) {
            int idx = i * 256 + tid;
            int kr = idx >> 5;
            int n0 = (idx & 31) * 4;
            float4 bv = *(const float4*)(Bm + (size_t)(k0 + kr) * ldb + col0 + n0);
            float vv[4] = {bv.x, bv.y, bv.z, bv.w};
            #pragma unroll
            for (int j = 0; j < 4; j++) {
                __nv_bfloat16 hi = __float2bfloat16(vv[j]);
                __nv_bfloat16 lo = __float2bfloat16(vv[j] - __bfloat162float(hi));
                sB[0][n0 + j][kr] = hi;
                sB[1][n0 + j][kr] = lo;
            }
        }
        __syncthreads();

        #pragma unroll
        for (int kk = 0; kk < 32; kk += 16) {
            uint32_t ah[2][4], al[2][4];
            #pragma unroll
            for (int mi = 0; mi < 2; mi++) {
                int r0 = wm * 32 + mi * 16;
                ah[mi][0] = *(const uint32_t*)&sA[0][r0 + g    ][kk + tg * 2];
                ah[mi][1] = *(const uint32_t*)&sA[0][r0 + g + 8][kk + tg * 2];
                ah[mi][2] = *(const uint32_t*)&sA[0][r0 + g    ][kk + tg * 2 + 8];
                ah[mi][3] = *(const uint32_t*)&sA[0][r0 + g + 8][kk + tg * 2 + 8];
                al[mi][0] = *(const uint32_t*)&sA[1][r0 + g    ][kk + tg * 2];
                al[mi][1] = *(const uint32_t*)&sA[1][r0 + g + 8][kk + tg * 2];
                al[mi][2] = *(const uint32_t*)&sA[1][r0 + g    ][kk + tg * 2 + 8];
                al[mi][3] = *(const uint32_t*)&sA[1][r0 + g + 8][kk + tg * 2 + 8];
            }
            uint32_t bh[8][2], bl[8][2];
            #pragma unroll
            for (int ni = 0; ni < 8; ni++) {
                int c0 = wn * 64 + ni * 8 + g;
                bh[ni][0] = *(const uint32_t*)&sB[0][c0][kk + tg * 2];
                bh[ni][1] = *(const uint32_t*)&sB[0][c0][kk + tg * 2 + 8];
                bl[ni][0] = *(const uint32_t*)&sB[1][c0][kk + tg * 2];
                bl[ni][1] = *(const uint32_t*)&sB[1][c0][kk + tg * 2 + 8];
            }
            #pragma unroll
            for (int mi = 0; mi < 2; mi++)
                #pragma unroll
                for (int ni = 0; ni < 8; ni++) {
                    MMA16816(acc[mi][ni], ah[mi], bh[ni]);
                    MMA16816(acc[mi][ni], ah[mi], bl[ni]);
                    MMA16816(acc[mi][ni], al[mi], bh[ni]);
                }
        }
        __syncthreads();
    }

    // ---- epilogue ----
    #pragma unroll
    for (int mi = 0; mi < 2; mi++) {
        int r = row0 + wm * 32 + mi * 16 + g;
        #pragma unroll
        for (int ni = 0; ni < 8; ni++) {
            int c = col0 + wn * 64 + ni * 8 + tg * 2;
            float v0 = acc[mi][ni][0], v1 = acc[mi][ni][1];
            float v2 = acc[mi][ni][2], v3 = acc[mi][ni][3];
            if (bias) {
                float b0 = bias[c], b1 = bias[c + 1];
                v0 += b0; v1 += b1; v2 += b0; v3 += b1;
            }
            if (res) {
                v0 += res[(size_t)r * ldc + c];
                v1 += res[(size_t)r * ldc + c + 1];
                v2 += res[(size_t)(r + 8) * ldc + c];
                v3 += res[(size_t)(r + 8) * ldc + c + 1];
            }
            if (doRelu) {
                v0 = fmaxf(v0, 0.0f); v1 = fmaxf(v1, 0.0f);
                v2 = fmaxf(v2, 0.0f); v3 = fmaxf(v3, 0.0f);
            }
            *(float2*)(C + (size_t)r * ldc + c)       = make_float2(v0, v1);
            *(float2*)(C + (size_t)(r + 8) * ldc + c) = make_float2(v2, v3);
        }
    }
}

// ---------------- attention: scores = scale * Q @ K^T, causal-tile skip ----------
__global__ void attn_scores_kernel(const float* __restrict__ q, const float* __restrict__ k) {
    int z = blockIdx.z;  int b = z >> 4;  int h = z & 15;
    int qt = blockIdx.y, kt = blockIdx.x;
    if (kt > qt) return;
    const float* A  = q + (size_t)b * T_ * E_ + h * HD_;
    const float* Bm = k + (size_t)b * T_ * E_ + h * HD_;
    float* C = g_scores + (size_t)z * T_ * T_;
    int row0 = qt * 64, col0 = kt * 64;
    __shared__ float As[16][65];
    __shared__ float Bs[16][65];
    int tid = threadIdx.x;
    int tx = tid & 15, ty = tid >> 4;
    int lm = tid >> 2;
    int lk = (tid & 3) * 4;
    float acc[4][4] = {};
    #pragma unroll
    for (int k0 = 0; k0 < HD_; k0 += 16) {
        float4 av = *(const float4*)(A + (size_t)(row0 + lm) * E_ + k0 + lk);
        As[lk + 0][lm] = av.x; As[lk + 1][lm] = av.y;
        As[lk + 2][lm] = av.z; As[lk + 3][lm] = av.w;
        float4 bv = *(const float4*)(Bm + (size_t)(col0 + lm) * E_ + k0 + lk);
        Bs[lk + 0][lm] = bv.x; Bs[lk + 1][lm] = bv.y;
        Bs[lk + 2][lm] = bv.z; Bs[lk + 3][lm] = bv.w;
        __syncthreads();
        #pragma unroll
        for (int kk = 0; kk < 16; kk++) {
            float a[4], bb[4];
            #pragma unroll
            for (int i = 0; i < 4; i++) a[i] = As[kk][ty * 4 + i];
            #pragma unroll
            for (int j = 0; j < 4; j++) bb[j] = Bs[kk][tx * 4 + j];
            #pragma unroll
            for (int i = 0; i < 4; i++)
                #pragma unroll
                for (int j = 0; j < 4; j++)
                    acc[i][j] += a[i] * bb[j];
        }
        __syncthreads();
    }
    #pragma unroll
    for (int i = 0; i < 4; i++)
        #pragma unroll
        for (int j = 0; j < 4; j++)
            C[(size_t)(row0 + ty * 4 + i) * T_ + col0 + tx * 4 + j] = acc[i][j] * SCALE_;
}

// ---------------- causal row softmax ----------------
__global__ void softmax_kernel() {
    int idx = blockIdx.x;
    int q = idx & (T_ - 1);
    float* row = g_scores + (size_t)idx * T_;
    int n = q + 1;
    int tid = threadIdx.x;
    float m = -1e30f;
    for (int i = tid; i < n; i += 256) m = fmaxf(m, row[i]);
    m = blockMax256(m);
    __syncthreads();
    float s = 0.0f;
    for (int i = tid; i < n; i += 256) {
        float e = __expf(row[i] - m);
        row[i] = e;
        s += e;
    }
    s = blockSum256(s);
    float inv = 1.0f / s;
    for (int i = tid; i < n; i += 256) row[i] *= inv;
    for (int i = n + tid; i < T_; i += 256) row[i] = 0.0f;
}

// ---------------- O = attn @ V ----------------
__global__ void attn_av_kernel(const float* __restrict__ v) {
    int z = blockIdx.z;  int b = z >> 4;  int h = z & 15;
    int qt = blockIdx.y;
    const float* A  = g_scores + (size_t)z * T_ * T_;
    const float* Bm = v + (size_t)b * T_ * E_ + h * HD_;
    float* C = g_o + (size_t)b * T_ * E_ + h * HD_;
    int row0 = qt * 64;
    int Kmax = row0 + 64;
    __shared__ float As[16][65];
    __shared__ float Bs[16][64];
    int tid = threadIdx.x;
    int tx = tid & 15, ty = tid >> 4;
    int lm = tid >> 2;
    int lk = (tid & 3) * 4;
    int bk = tid >> 4;
    int bn = (tid & 15) * 4;
    float acc[4][4] = {};
    for (int k0 = 0; k0 < Kmax; k0 += 16) {
        float4 av = *(const float4*)(A + (size_t)(row0 + lm) * T_ + k0 + lk);
        As[lk + 0][lm] = av.x; As[lk + 1][lm] = av.y;
        As[lk + 2][lm] = av.z; As[lk + 3][lm] = av.w;
        *(float4*)&Bs[bk][bn] = *(const float4*)(Bm + (size_t)(k0 + bk) * E_ + bn);
        __syncthreads();
        #pragma unroll
        for (int kk = 0; kk < 16; kk++) {
            float a[4], bb[4];
            #pragma unroll
            for (int i = 0; i < 4; i++) a[i] = As[kk][ty * 4 + i];
            #pragma unroll
            for (int j = 0; j < 4; j++) bb[j] = Bs[kk][tx * 4 + j];
            #pragma unroll
            for (int i = 0; i < 4; i++)
                #pragma unroll
                for (int j = 0; j < 4; j++)
                    acc[i][j] += a[i] * bb[j];
        }
        __syncthreads();
    }
    #pragma unroll
    for (int i = 0; i < 4; i++)
        #pragma unroll
        for (int j = 0; j < 4; j++)
            C[(size_t)(row0 + ty * 4 + i) * E_ + tx * 4 + j] = acc[i][j];
}

// ---------------- loss ----------------
__global__ void rowloss_kernel(const float* __restrict__ logits, const int* __restrict__ tgt) {
    int row = blockIdx.x;
    const float* lr = logits + (size_t)row * V_;
    int tid = threadIdx.x;
    float m = -1e30f;
    for (int i = tid; i < V_; i += 256) m = fmaxf(m, lr[i]);
    m = blockMax256(m);
    __syncthreads();
    float s = 0.0f;
    for (int i = tid; i < V_; i += 256) s += __expf(lr[i] - m);
    s = blockSum256(s);
    if (tid == 0)
        g_rowloss[row] = -(lr[tgt[row]] - m - logf(s));
}

__global__ void loss_final_kernel(float* __restrict__ dst) {
    int tid = threadIdx.x;
    float s = 0.0f;
    for (int i = tid; i < BT_; i += 256) s += g_rowloss[i];
    s = blockSum256(s);
    if (tid == 0) dst[0] = s * (1.0f / BT_);
}

// ---------------- host driver ----------------
extern "C" void kernel_launch(void* const* d_in, const int* in_sizes, int n_in,
                              void* d_out, int out_size) {
    const int*   context = (const int*)  d_in[0];
    const int*   targets = (const int*)  d_in[1];
    const float* tok_emb = (const float*)d_in[2];
    const float* pos_emb = (const float*)d_in[3];
    const float* Wq    = (const float*)d_in[4];
    const float* Wk    = (const float*)d_in[5];
    const float* Wv    = (const float*)d_in[6];
    const float* Wo    = (const float*)d_in[7];
    const float* bo    = (const float*)d_in[8];
    const float* ln1_g = (const float*)d_in[9];
    const float* ln1_b = (const float*)d_in[10];
    const float* ln2_g = (const float*)d_in[11];
    const float* ln2_b = (const float*)d_in[12];
    const float* W1    = (const float*)d_in[13];
    const float* b1    = (const float*)d_in[14];
    const float* W2    = (const float*)d_in[15];
    const float* b2    = (const float*)d_in[16];
    const float* lnf_g = (const float*)d_in[17];
    const float* lnf_b = (const float*)d_in[18];
    const float* Wlm   = (const float*)d_in[19];
    const float* blm   = (const float*)d_in[20];

    float *x, *h, *q, *k, *v, *o, *ff, *logits_sym, *lossdummy;
    cudaGetSymbolAddress((void**)&x,  g_x);
    cudaGetSymbolAddress((void**)&h,  g_h);
    cudaGetSymbolAddress((void**)&q,  g_q);
    cudaGetSymbolAddress((void**)&k,  g_k);
    cudaGetSymbolAddress((void**)&v,  g_v);
    cudaGetSymbolAddress((void**)&o,  g_o);
    cudaGetSymbolAddress((void**)&ff, g_ff);
    cudaGetSymbolAddress((void**)&logits_sym, g_logits);
    cudaGetSymbolAddress((void**)&lossdummy,  g_lossdummy);

    const long long BTV = (long long)BT_ * V_;
    float* out = (float*)d_out;
    float* logits = ((long long)out_size >= BTV) ? out : logits_sym;
    float* lossdst;
    if ((long long)out_size > BTV)       lossdst = out + BTV;
    else if ((long long)out_size < BTV)  lossdst = out;
    else                                 lossdst = lossdummy;

    embed_kernel<<<(BT_ * E_) / 256, 256>>>(context, tok_emb, pos_emb);

    dim3 gE(E_ / 128, BT_ / 128);      // 8 x 16
    dim3 gFF(FF_ / 128, BT_ / 128);    // 32 x 16
    dim3 gV2(V_ / 128, BT_ / 128);     // 250 x 16
    dim3 gS(T_ / 64, T_ / 64, B_ * H_);
    dim3 gAV(1, T_ / 64, B_ * H_);

    for (int l = 0; l < L_; l++) {
        const float* wq = Wq + (size_t)l * E_ * E_;
        const float* wk = Wk + (size_t)l * E_ * E_;
        const float* wv = Wv + (size_t)l * E_ * E_;
        const float* wo = Wo + (size_t)l * E_ * E_;
        const float* w1 = W1 + (size_t)l * E_ * FF_;
        const float* w2 = W2 + (size_t)l * FF_ * E_;

        ln_kernel<<<BT_, 256>>>(x, h, ln1_g + l * E_, ln1_b + l * E_);
        mma_gemm<<<gE, 256>>>(h, wq, nullptr, nullptr, q, BT_, E_, E_, E_, E_, E_, 0);
        mma_gemm<<<gE, 256>>>(h, wk, nullptr, nullptr, k, BT_, E_, E_, E_, E_, E_, 0);
        mma_gemm<<<gE, 256>>>(h, wv, nullptr, nullptr, v, BT_, E_, E_, E_, E_, E_, 0);
        attn_scores_kernel<<<gS, 256>>>(q, k);
        softmax_kernel<<<B_ * H_ * T_, 256>>>();
        attn_av_kernel<<<gAV, 256>>>(v);
        mma_gemm<<<gE, 256>>>(o, wo, bo + l * E_, x, x, BT_, E_, E_, E_, E_, E_, 0);
        ln_kernel<<<BT_, 256>>>(x, h, ln2_g + l * E_, ln2_b + l * E_);
        mma_gemm<<<gFF, 256>>>(h, w1, b1 + l * FF_, nullptr, ff, BT_, FF_, E_, E_, FF_, FF_, 1);
        mma_gemm<<<gE, 256>>>(ff, w2, b2 + l * E_, x, x, BT_, E_, FF_, FF_, E_, E_, 0);
    }

    ln_kernel<<<BT_, 256>>>(x, h, lnf_g, lnf_b);
    mma_gemm<<<gV2, 256>>>(h, Wlm, blm, nullptr, logits, BT_, V_, E_, E_, V_, V_, 0);

    rowloss_kernel<<<BT_, 256>>>(logits, targets);
    loss_final_kernel<<<1, 256>>>(lossdst);
}

// round 6
// speedup vs baseline: 2.1542x; 1.5701x over previous
#include <cuda_runtime.h>
#include <cuda_bf16.h>
#include <stdint.h>
#include <math.h>

// ---------------- problem constants ----------------
#define B_   2
#define T_   1024
#define E_   1024
#define H_   16
#define HD_  64
#define L_   8
#define FF_  4096
#define V_   32000
#define BT_  (B_ * T_)
#define EPS_ 1e-5f
#define SCALE_ 0.03125f   // 1/sqrt(E)

// ---------------- scratch (device globals; no allocation allowed) ----------------
__device__ float g_x[BT_ * E_];
__device__ float g_h[BT_ * E_];
__device__ float g_qkv[BT_ * 3 * E_];
__device__ float g_o[BT_ * E_];
__device__ float g_ff[(size_t)BT_ * FF_];
__device__ float g_scores[(size_t)B_ * H_ * T_ * T_];
__device__ float g_logits[(size_t)BT_ * V_];
__device__ float g_rowloss[BT_];
__device__ float g_lossdummy[4];
// bf16 split planes
__device__ __nv_bfloat16 g_ahi[(size_t)BT_ * FF_];
__device__ __nv_bfloat16 g_alo[(size_t)BT_ * FF_];
__device__ __nv_bfloat16 g_wthi[(size_t)V_ * E_];
__device__ __nv_bfloat16 g_wtlo[(size_t)V_ * E_];

// ---------------- reductions (blockDim.x == 256) ----------------
__device__ __forceinline__ float blockSum256(float v) {
    __shared__ float sh[8];
    int tid = threadIdx.x;
    #pragma unroll
    for (int o = 16; o; o >>= 1) v += __shfl_xor_sync(0xffffffffu, v, o);
    __syncthreads();
    if ((tid & 31) == 0) sh[tid >> 5] = v;
    __syncthreads();
    v = sh[tid & 7];
    #pragma unroll
    for (int o = 4; o; o >>= 1) v += __shfl_xor_sync(0xffffffffu, v, o);
    return v;
}

__device__ __forceinline__ float blockMax256(float v) {
    __shared__ float sh[8];
    int tid = threadIdx.x;
    #pragma unroll
    for (int o = 16; o; o >>= 1) v = fmaxf(v, __shfl_xor_sync(0xffffffffu, v, o));
    __syncthreads();
    if ((tid & 31) == 0) sh[tid >> 5] = v;
    __syncthreads();
    v = sh[tid & 7];
    #pragma unroll
    for (int o = 4; o; o >>= 1) v = fmaxf(v, __shfl_xor_sync(0xffffffffu, v, o));
    return v;
}

// ---------------- embedding ----------------
__global__ void embed_kernel(const int* __restrict__ ctx,
                             const float* __restrict__ tok,
                             const float* __restrict__ pos) {
    int gid = blockIdx.x * blockDim.x + threadIdx.x;
    int bt = gid >> 10;
    int e  = gid & (E_ - 1);
    int t  = bt & (T_ - 1);
    g_x[gid] = tok[(size_t)ctx[bt] * E_ + e] + pos[t * E_ + e];
}

// ---------------- layernorm ----------------
__global__ void ln_kernel(const float* __restrict__ in, float* __restrict__ out,
                          const float* __restrict__ g, const float* __restrict__ b) {
    int row = blockIdx.x;
    int tid = threadIdx.x;
    const float4* rp = (const float4*)(in + (size_t)row * E_);
    float4 v = rp[tid];
    float s  = v.x + v.y + v.z + v.w;
    float ss = v.x * v.x + v.y * v.y + v.z * v.z + v.w * v.w;
    s  = blockSum256(s);
    __syncthreads();
    ss = blockSum256(ss);
    float mean = s * (1.0f / E_);
    float var  = ss * (1.0f / E_) - mean * mean;
    float inv  = rsqrtf(var + EPS_);
    int e = tid * 4;
    float4 o;
    o.x = (v.x - mean) * inv * g[e + 0] + b[e + 0];
    o.y = (v.y - mean) * inv * g[e + 1] + b[e + 1];
    o.z = (v.z - mean) * inv * g[e + 2] + b[e + 2];
    o.w = (v.w - mean) * inv * g[e + 3] + b[e + 3];
    ((float4*)(out + (size_t)row * E_))[tid] = o;
}

// ---------------- activation split: fp32 -> bf16 hi/lo planes ----------------
__global__ void act_split(const float* __restrict__ in,
                          __nv_bfloat16* __restrict__ hi,
                          __nv_bfloat16* __restrict__ lo) {
    size_t i = (size_t)blockIdx.x * blockDim.x + threadIdx.x;  // one float4 per thread
    float4 v = ((const float4*)in)[i];
    float vv[4] = {v.x, v.y, v.z, v.w};
    ushort4 ho, lw;
    unsigned short* hp = &ho.x;
    unsigned short* lp = &lw.x;
    #pragma unroll
    for (int j = 0; j < 4; j++) {
        __nv_bfloat16 h = __float2bfloat16(vv[j]);
        __nv_bfloat16 l = __float2bfloat16(vv[j] - __bfloat162float(h));
        hp[j] = __bfloat16_as_ushort(h);
        lp[j] = __bfloat16_as_ushort(l);
    }
    ((ushort4*)hi)[i] = ho;
    ((ushort4*)lo)[i] = lw;
}

// ---------------- weight transpose+split: W[K,N] fp32 -> T[N,K] bf16 hi/lo --------
__global__ void wt_tsplit(const float* __restrict__ W,
                          __nv_bfloat16* __restrict__ Thi,
                          __nv_bfloat16* __restrict__ Tlo,
                          int N, int K) {
    __shared__ float s[32][33];
    int n0 = blockIdx.x * 32;
    int k0 = blockIdx.y * 32;
    int tx = threadIdx.x;   // 0..7
    int ty = threadIdx.y;   // 0..31
    // read: rows k0+ty, cols n0 + tx*4..+3
    float4 rv = *(const float4*)(W + (size_t)(k0 + ty) * N + n0 + tx * 4);
    s[ty][tx * 4 + 0] = rv.x;
    s[ty][tx * 4 + 1] = rv.y;
    s[ty][tx * 4 + 2] = rv.z;
    s[ty][tx * 4 + 3] = rv.w;
    __syncthreads();
    // write: out row n0+ty, k chunk k0 + tx*4..+3
    ushort4 ho, lw;
    unsigned short* hp = &ho.x;
    unsigned short* lp = &lw.x;
    #pragma unroll
    for (int j = 0; j < 4; j++) {
        float f = s[tx * 4 + j][ty];
        __nv_bfloat16 h = __float2bfloat16(f);
        __nv_bfloat16 l = __float2bfloat16(f - __bfloat162float(h));
        hp[j] = __bfloat16_as_ushort(h);
        lp[j] = __bfloat16_as_ushort(l);
    }
    size_t off = (size_t)(n0 + ty) * K + k0 + tx * 4;
    *(ushort4*)(Thi + off) = ho;
    *(ushort4*)(Tlo + off) = lw;
}

// ============ bf16x3 split tensor-core GEMM, cp.async double-buffered ============
// C = A(MxK) @ Bt(NxK)^T (+bias +res, relu). A/Bt pre-split bf16 hi/lo, k-contiguous.
// 128x128x32 tiles, 256 threads (8 warps), 2-stage pipeline.
#define MMA16816(c, a, b) \
  asm volatile("mma.sync.aligned.m16n8k16.row.col.f32.bf16.bf16.f32 " \
    "{%0,%1,%2,%3}, {%4,%5,%6,%7}, {%8,%9}, {%0,%1,%2,%3};" \
    : "+f"((c)[0]), "+f"((c)[1]), "+f"((c)[2]), "+f"((c)[3]) \
    : "r"((a)[0]), "r"((a)[1]), "r"((a)[2]), "r"((a)[3]), \
      "r"((b)[0]), "r"((b)[1]))

#define CP16(dst_u32, src) \
  asm volatile("cp.async.cg.shared.global [%0], [%1], 16;" :: "r"(dst_u32), "l"(src))

// smem halves layout: stage*20480 + mat*5120 + row*40 + k    (mat: 0=Ahi 1=Alo 2=Bhi 3=Blo)
#define SM_STAGE 20480
#define SM_MAT   5120
#define SM_ROW   40

__global__ void __launch_bounds__(256) mma_gemm(
        const __nv_bfloat16* __restrict__ Ahi, const __nv_bfloat16* __restrict__ Alo,
        const __nv_bfloat16* __restrict__ Bthi, const __nv_bfloat16* __restrict__ Btlo,
        const float* __restrict__ bias, const float* __restrict__ res,
        float* __restrict__ C, int M, int N, int K, int ldc, int doRelu) {
    extern __shared__ __nv_bfloat16 smem[];

    int tid  = threadIdx.x;
    int warp = tid >> 5, lane = tid & 31;
    int wm = warp & 3;
    int wn = warp >> 2;
    int g  = lane >> 2;
    int tg = lane & 3;

    int row0 = blockIdx.y * 128;
    int col0 = blockIdx.x * 128;

    const __nv_bfloat16* planes[4] = {Ahi, Alo, Bthi, Btlo};

    // per-thread load slots: 2 chunks (16B each) per matrix plane
    int r_a = tid >> 1;                 // not used; explicit below
    (void)r_a;
    unsigned smem_base_u32 = (unsigned)__cvta_generic_to_shared(smem);

    float acc[2][8][4];
    #pragma unroll
    for (int i = 0; i < 2; i++)
        #pragma unroll
        for (int j = 0; j < 8; j++)
            #pragma unroll
            for (int r = 0; r < 4; r++) acc[i][j][r] = 0.0f;

    int nk = K >> 5;   // K / 32

    // ---- loader ----
    auto load_stage = [&](int stage, int k0) {
        #pragma unroll
        for (int m = 0; m < 4; m++) {
            const __nv_bfloat16* P = planes[m];
            int base_row = (m < 2) ? row0 : col0;
            #pragma unroll
            for (int rep = 0; rep < 2; rep++) {
                int chunk = rep * 256 + tid;
                int row = chunk >> 2;
                int kc  = chunk & 3;
                unsigned dst = smem_base_u32 +
                    2u * (stage * SM_STAGE + m * SM_MAT + row * SM_ROW + kc * 8);
                const __nv_bfloat16* src = P + (size_t)(base_row + row) * K + k0 + kc * 8;
                CP16(dst, src);
            }
        }
        asm volatile("cp.async.commit_group;");
    };

    load_stage(0, 0);

    for (int kt = 0; kt < nk; kt++) {
        if (kt + 1 < nk) {
            load_stage((kt + 1) & 1, (kt + 1) << 5);
            asm volatile("cp.async.wait_group 1;");
        } else {
            asm volatile("cp.async.wait_group 0;");
        }
        __syncthreads();

        const __nv_bfloat16* sAhi = smem + (kt & 1) * SM_STAGE;
        const __nv_bfloat16* sAlo = sAhi + SM_MAT;
        const __nv_bfloat16* sBhi = sAhi + 2 * SM_MAT;
        const __nv_bfloat16* sBlo = sAhi + 3 * SM_MAT;

        #pragma unroll
        for (int kk = 0; kk < 32; kk += 16) {
            uint32_t ah[2][4], al[2][4];
            #pragma unroll
            for (int mi = 0; mi < 2; mi++) {
                int r0 = wm * 32 + mi * 16;
                int h0 = kk + tg * 2;
                ah[mi][0] = *(const uint32_t*)(sAhi + (r0 + g    ) * SM_ROW + h0);
                ah[mi][1] = *(const uint32_t*)(sAhi + (r0 + g + 8) * SM_ROW + h0);
                ah[mi][2] = *(const uint32_t*)(sAhi + (r0 + g    ) * SM_ROW + h0 + 8);
                ah[mi][3] = *(const uint32_t*)(sAhi + (r0 + g + 8) * SM_ROW + h0 + 8);
                al[mi][0] = *(const uint32_t*)(sAlo + (r0 + g    ) * SM_ROW + h0);
                al[mi][1] = *(const uint32_t*)(sAlo + (r0 + g + 8) * SM_ROW + h0);
                al[mi][2] = *(const uint32_t*)(sAlo + (r0 + g    ) * SM_ROW + h0 + 8);
                al[mi][3] = *(const uint32_t*)(sAlo + (r0 + g + 8) * SM_ROW + h0 + 8);
            }
            #pragma unroll
            for (int ni = 0; ni < 8; ni++) {
                int c0 = wn * 64 + ni * 8 + g;
                int h0 = kk + tg * 2;
                uint32_t bh[2], bl[2];
                bh[0] = *(const uint32_t*)(sBhi + c0 * SM_ROW + h0);
                bh[1] = *(const uint32_t*)(sBhi + c0 * SM_ROW + h0 + 8);
                bl[0] = *(const uint32_t*)(sBlo + c0 * SM_ROW + h0);
                bl[1] = *(const uint32_t*)(sBlo + c0 * SM_ROW + h0 + 8);
                #pragma unroll
                for (int mi = 0; mi < 2; mi++) {
                    MMA16816(acc[mi][ni], ah[mi], bh);
                    MMA16816(acc[mi][ni], ah[mi], bl);
                    MMA16816(acc[mi][ni], al[mi], bh);
                }
            }
        }
        __syncthreads();
    }

    // ---- epilogue ----
    #pragma unroll
    for (int mi = 0; mi < 2; mi++) {
        int r = row0 + wm * 32 + mi * 16 + g;
        #pragma unroll
        for (int ni = 0; ni < 8; ni++) {
            int c = col0 + wn * 64 + ni * 8 + tg * 2;
            float v0 = acc[mi][ni][0], v1 = acc[mi][ni][1];
            float v2 = acc[mi][ni][2], v3 = acc[mi][ni][3];
            if (bias) {
                float b0 = bias[c], b1 = bias[c + 1];
                v0 += b0; v1 += b1; v2 += b0; v3 += b1;
            }
            if (res) {
                v0 += res[(size_t)r * ldc + c];
                v1 += res[(size_t)r * ldc + c + 1];
                v2 += res[(size_t)(r + 8) * ldc + c];
                v3 += res[(size_t)(r + 8) * ldc + c + 1];
            }
            if (doRelu) {
                v0 = fmaxf(v0, 0.0f); v1 = fmaxf(v1, 0.0f);
                v2 = fmaxf(v2, 0.0f); v3 = fmaxf(v3, 0.0f);
            }
            *(float2*)(C + (size_t)r * ldc + c)       = make_float2(v0, v1);
            *(float2*)(C + (size_t)(r + 8) * ldc + c) = make_float2(v2, v3);
        }
    }
}

// ---------------- attention: scores = scale * Q @ K^T (strided qkv) --------------
__global__ void attn_scores_kernel() {
    int z = blockIdx.z;  int b = z >> 4;  int h = z & 15;
    int qt = blockIdx.y, kt = blockIdx.x;
    if (kt > qt) return;
    const float* A  = g_qkv + (size_t)b * T_ * 3 * E_ + h * HD_;            // q
    const float* Bm = g_qkv + (size_t)b * T_ * 3 * E_ + E_ + h * HD_;       // k
    const int lda = 3 * E_;
    float* C = g_scores + (size_t)z * T_ * T_;
    int row0 = qt * 64, col0 = kt * 64;
    __shared__ float As[16][65];
    __shared__ float Bs[16][65];
    int tid = threadIdx.x;
    int tx = tid & 15, ty = tid >> 4;
    int lm = tid >> 2;
    int lk = (tid & 3) * 4;
    float acc[4][4] = {};
    #pragma unroll
    for (int k0 = 0; k0 < HD_; k0 += 16) {
        float4 av = *(const float4*)(A + (size_t)(row0 + lm) * lda + k0 + lk);
        As[lk + 0][lm] = av.x; As[lk + 1][lm] = av.y;
        As[lk + 2][lm] = av.z; As[lk + 3][lm] = av.w;
        float4 bv = *(const float4*)(Bm + (size_t)(col0 + lm) * lda + k0 + lk);
        Bs[lk + 0][lm] = bv.x; Bs[lk + 1][lm] = bv.y;
        Bs[lk + 2][lm] = bv.z; Bs[lk + 3][lm] = bv.w;
        __syncthreads();
        #pragma unroll
        for (int kk = 0; kk < 16; kk++) {
            float a[4], bb[4];
            #pragma unroll
            for (int i = 0; i < 4; i++) a[i] = As[kk][ty * 4 + i];
            #pragma unroll
            for (int j = 0; j < 4; j++) bb[j] = Bs[kk][tx * 4 + j];
            #pragma unroll
            for (int i = 0; i < 4; i++)
                #pragma unroll
                for (int j = 0; j < 4; j++)
                    acc[i][j] += a[i] * bb[j];
        }
        __syncthreads();
    }
    #pragma unroll
    for (int i = 0; i < 4; i++)
        #pragma unroll
        for (int j = 0; j < 4; j++)
            C[(size_t)(row0 + ty * 4 + i) * T_ + col0 + tx * 4 + j] = acc[i][j] * SCALE_;
}

// ---------------- causal row softmax ----------------
__global__ void softmax_kernel() {
    int idx = blockIdx.x;
    int q = idx & (T_ - 1);
    float* row = g_scores + (size_t)idx * T_;
    int n = q + 1;
    int tid = threadIdx.x;
    float m = -1e30f;
    for (int i = tid; i < n; i += 256) m = fmaxf(m, row[i]);
    m = blockMax256(m);
    __syncthreads();
    float s = 0.0f;
    for (int i = tid; i < n; i += 256) {
        float e = __expf(row[i] - m);
        row[i] = e;
        s += e;
    }
    s = blockSum256(s);
    float inv = 1.0f / s;
    for (int i = tid; i < n; i += 256) row[i] *= inv;
    for (int i = n + tid; i < T_; i += 256) row[i] = 0.0f;
}

// ---------------- O = attn @ V (strided qkv) ----------------
__global__ void attn_av_kernel() {
    int z = blockIdx.z;  int b = z >> 4;  int h = z & 15;
    int qt = blockIdx.y;
    const float* A  = g_scores + (size_t)z * T_ * T_;
    const float* Bm = g_qkv + (size_t)b * T_ * 3 * E_ + 2 * E_ + h * HD_;   // v
    const int ldb = 3 * E_;
    float* C = g_o + (size_t)b * T_ * E_ + h * HD_;
    int row0 = qt * 64;
    int Kmax = row0 + 64;
    __shared__ float As[16][65];
    __shared__ float Bs[16][64];
    int tid = threadIdx.x;
    int tx = tid & 15, ty = tid >> 4;
    int lm = tid >> 2;
    int lk = (tid & 3) * 4;
    int bk = tid >> 4;
    int bn = (tid & 15) * 4;
    float acc[4][4] = {};
    for (int k0 = 0; k0 < Kmax; k0 += 16) {
        float4 av = *(const float4*)(A + (size_t)(row0 + lm) * T_ + k0 + lk);
        As[lk + 0][lm] = av.x; As[lk + 1][lm] = av.y;
        As[lk + 2][lm] = av.z; As[lk + 3][lm] = av.w;
        *(float4*)&Bs[bk][bn] = *(const float4*)(Bm + (size_t)(k0 + bk) * ldb + bn);
        __syncthreads();
        #pragma unroll
        for (int kk = 0; kk < 16; kk++) {
            float a[4], bb[4];
            #pragma unroll
            for (int i = 0; i < 4; i++) a[i] = As[kk][ty * 4 + i];
            #pragma unroll
            for (int j = 0; j < 4; j++) bb[j] = Bs[kk][tx * 4 + j];
            #pragma unroll
            for (int i = 0; i < 4; i++)
                #pragma unroll
                for (int j = 0; j < 4; j++)
                    acc[i][j] += a[i] * bb[j];
        }
        __syncthreads();
    }
    #pragma unroll
    for (int i = 0; i < 4; i++)
        #pragma unroll
        for (int j = 0; j < 4; j++)
            C[(size_t)(row0 + ty * 4 + i) * E_ + tx * 4 + j] = acc[i][j];
}

// ---------------- loss ----------------
__global__ void rowloss_kernel(const float* __restrict__ logits, const int* __restrict__ tgt) {
    int row = blockIdx.x;
    const float* lr = logits + (size_t)row * V_;
    int tid = threadIdx.x;
    float m = -1e30f;
    for (int i = tid; i < V_; i += 256) m = fmaxf(m, lr[i]);
    m = blockMax256(m);
    __syncthreads();
    float s = 0.0f;
    for (int i = tid; i < V_; i += 256) s += __expf(lr[i] - m);
    s = blockSum256(s);
    if (tid == 0)
        g_rowloss[row] = -(lr[tgt[row]] - m - logf(s));
}

__global__ void loss_final_kernel(float* __restrict__ dst) {
    int tid = threadIdx.x;
    float s = 0.0f;
    for (int i = tid; i < BT_; i += 256) s += g_rowloss[i];
    s = blockSum256(s);
    if (tid == 0) dst[0] = s * (1.0f / BT_);
}

// ---------------- host driver ----------------
#define GEMM_SMEM 81920

extern "C" void kernel_launch(void* const* d_in, const int* in_sizes, int n_in,
                              void* d_out, int out_size) {
    const int*   context = (const int*)  d_in[0];
    const int*   targets = (const int*)  d_in[1];
    const float* tok_emb = (const float*)d_in[2];
    const float* pos_emb = (const float*)d_in[3];
    const float* Wq    = (const float*)d_in[4];
    const float* Wk    = (const float*)d_in[5];
    const float* Wv    = (const float*)d_in[6];
    const float* Wo    = (const float*)d_in[7];
    const float* bo    = (const float*)d_in[8];
    const float* ln1_g = (const float*)d_in[9];
    const float* ln1_b = (const float*)d_in[10];
    const float* ln2_g = (const float*)d_in[11];
    const float* ln2_b = (const float*)d_in[12];
    const float* W1    = (const float*)d_in[13];
    const float* b1    = (const float*)d_in[14];
    const float* W2    = (const float*)d_in[15];
    const float* b2    = (const float*)d_in[16];
    const float* lnf_g = (const float*)d_in[17];
    const float* lnf_b = (const float*)d_in[18];
    const float* Wlm   = (const float*)d_in[19];
    const float* blm   = (const float*)d_in[20];

    float *x, *h, *qkv, *o, *ff, *logits_sym, *lossdummy;
    __nv_bfloat16 *ahi, *alo, *wthi, *wtlo;
    cudaGetSymbolAddress((void**)&x,   g_x);
    cudaGetSymbolAddress((void**)&h,   g_h);
    cudaGetSymbolAddress((void**)&qkv, g_qkv);
    cudaGetSymbolAddress((void**)&o,   g_o);
    cudaGetSymbolAddress((void**)&ff,  g_ff);
    cudaGetSymbolAddress((void**)&logits_sym, g_logits);
    cudaGetSymbolAddress((void**)&lossdummy,  g_lossdummy);
    cudaGetSymbolAddress((void**)&ahi, g_ahi);
    cudaGetSymbolAddress((void**)&alo, g_alo);
    cudaGetSymbolAddress((void**)&wthi, g_wthi);
    cudaGetSymbolAddress((void**)&wtlo, g_wtlo);

    cudaFuncSetAttribute(mma_gemm, cudaFuncAttributeMaxDynamicSharedMemorySize, GEMM_SMEM);

    const long long BTV = (long long)BT_ * V_;
    float* out = (float*)d_out;
    float* logits = ((long long)out_size >= BTV) ? out : logits_sym;
    float* lossdst;
    if ((long long)out_size > BTV)       lossdst = out + BTV;
    else if ((long long)out_size < BTV)  lossdst = out;
    else                                 lossdst = lossdummy;

    embed_kernel<<<(BT_ * E_) / 256, 256>>>(context, tok_emb, pos_emb);

    dim3 gQKV(3 * E_ / 128, BT_ / 128);   // 24 x 16 = 384
    dim3 gE(E_ / 128, BT_ / 128);         // 8 x 16 = 128
    dim3 gFF(FF_ / 128, BT_ / 128);       // 32 x 16 = 512
    dim3 gV2(V_ / 128, BT_ / 128);        // 250 x 16 = 4000
    dim3 gS(T_ / 64, T_ / 64, B_ * H_);
    dim3 gAV(1, T_ / 64, B_ * H_);
    dim3 tT(8, 32);

    for (int l = 0; l < L_; l++) {
        const float* wq = Wq + (size_t)l * E_ * E_;
        const float* wk = Wk + (size_t)l * E_ * E_;
        const float* wv = Wv + (size_t)l * E_ * E_;
        const float* wo = Wo + (size_t)l * E_ * E_;
        const float* w1 = W1 + (size_t)l * E_ * FF_;
        const float* w2 = W2 + (size_t)l * FF_ * E_;

        // ---- attention block ----
        ln_kernel<<<BT_, 256>>>(x, h, ln1_g + l * E_, ln1_b + l * E_);
        act_split<<<(BT_ * E_ / 4) / 256, 256>>>(h, ahi, alo);
        wt_tsplit<<<dim3(E_ / 32, E_ / 32), tT>>>(wq, wthi,                alo ? wtlo : wtlo, E_, E_);
        wt_tsplit<<<dim3(E_ / 32, E_ / 32), tT>>>(wk, wthi + (size_t)E_ * E_,     wtlo + (size_t)E_ * E_,     E_, E_);
        wt_tsplit<<<dim3(E_ / 32, E_ / 32), tT>>>(wv, wthi + (size_t)2 * E_ * E_, wtlo + (size_t)2 * E_ * E_, E_, E_);
        mma_gemm<<<gQKV, 256, GEMM_SMEM>>>(ahi, alo, wthi, wtlo, nullptr, nullptr,
                                           qkv, BT_, 3 * E_, E_, 3 * E_, 0);
        attn_scores_kernel<<<gS, 256>>>();
        softmax_kernel<<<B_ * H_ * T_, 256>>>();
        attn_av_kernel<<<gAV, 256>>>();
        act_split<<<(BT_ * E_ / 4) / 256, 256>>>(o, ahi, alo);
        wt_tsplit<<<dim3(E_ / 32, E_ / 32), tT>>>(wo, wthi, wtlo, E_, E_);
        mma_gemm<<<gE, 256, GEMM_SMEM>>>(ahi, alo, wthi, wtlo, bo + l * E_, x,
                                         x, BT_, E_, E_, E_, 0);

        // ---- MLP block ----
        ln_kernel<<<BT_, 256>>>(x, h, ln2_g + l * E_, ln2_b + l * E_);
        act_split<<<(BT_ * E_ / 4) / 256, 256>>>(h, ahi, alo);
        wt_tsplit<<<dim3(FF_ / 32, E_ / 32), tT>>>(w1, wthi, wtlo, FF_, E_);
        mma_gemm<<<gFF, 256, GEMM_SMEM>>>(ahi, alo, wthi, wtlo, b1 + l * FF_, nullptr,
                                          ff, BT_, FF_, E_, FF_, 1);
        act_split<<<((size_t)BT_ * FF_ / 4) / 256, 256>>>(ff, ahi, alo);
        wt_tsplit<<<dim3(E_ / 32, FF_ / 32), tT>>>(w2, wthi, wtlo, E_, FF_);
        mma_gemm<<<gE, 256, GEMM_SMEM>>>(ahi, alo, wthi, wtlo, b2 + l * E_, x,
                                         x, BT_, E_, FF_, E_, 0);
    }

    // ---- final LN + LM head ----
    ln_kernel<<<BT_, 256>>>(x, h, lnf_g, lnf_b);
    act_split<<<(BT_ * E_ / 4) / 256, 256>>>(h, ahi, alo);
    wt_tsplit<<<dim3(V_ / 32, E_ / 32), tT>>>(Wlm, wthi, wtlo, V_, E_);
    mma_gemm<<<gV2, 256, GEMM_SMEM>>>(ahi, alo, wthi, wtlo, blm, nullptr,
                                      logits, BT_, V_, E_, V_, 0);

    rowloss_kernel<<<BT_, 256>>>(logits, targets);
    loss_final_kernel<<<1, 256>>>(lossdst);
}

// round 8
// speedup vs baseline: 2.4265x; 1.1264x over previous
#include <cuda_runtime.h>
#include <cuda_bf16.h>
#include <stdint.h>
#include <math.h>

// ---------------- problem constants ----------------
#define B_   2
#define T_   1024
#define E_   1024
#define H_   16
#define HD_  64
#define L_   8
#define FF_  4096
#define V_   32000
#define BT_  (B_ * T_)
#define EPS_ 1e-5f
#define SCALE_ 0.03125f   // 1/sqrt(E)

typedef __nv_bfloat16 bf16;

// ---------------- scratch (device globals) ----------------
__device__ float g_x[BT_ * E_];
__device__ float g_scores[(size_t)B_ * H_ * T_ * T_];
__device__ float g_logits[(size_t)BT_ * V_];
__device__ float g_rowloss[BT_];
__device__ float g_lossdummy[4];
// bf16 split planes
__device__ bf16 g_hhi[BT_ * E_];
__device__ bf16 g_hlo[BT_ * E_];
__device__ bf16 g_qkvhi[BT_ * 3 * E_];
__device__ bf16 g_qkvlo[BT_ * 3 * E_];
__device__ bf16 g_vthi[(size_t)B_ * H_ * HD_ * T_];
__device__ bf16 g_vtlo[(size_t)B_ * H_ * HD_ * T_];
__device__ bf16 g_phi[(size_t)B_ * H_ * T_ * T_];
__device__ bf16 g_plo[(size_t)B_ * H_ * T_ * T_];
__device__ bf16 g_ffhi[(size_t)BT_ * FF_];
__device__ bf16 g_fflo[(size_t)BT_ * FF_];
__device__ bf16 g_ohi[BT_ * E_];
__device__ bf16 g_olo[BT_ * E_];
__device__ bf16 g_wthi[(size_t)V_ * E_];
__device__ bf16 g_wtlo[(size_t)V_ * E_];

// ---------------- reductions (blockDim.x == 256) ----------------
__device__ __forceinline__ float blockSum256(float v) {
    __shared__ float sh[8];
    int tid = threadIdx.x;
    #pragma unroll
    for (int o = 16; o; o >>= 1) v += __shfl_xor_sync(0xffffffffu, v, o);
    __syncthreads();
    if ((tid & 31) == 0) sh[tid >> 5] = v;
    __syncthreads();
    v = sh[tid & 7];
    #pragma unroll
    for (int o = 4; o; o >>= 1) v += __shfl_xor_sync(0xffffffffu, v, o);
    return v;
}

__device__ __forceinline__ float blockMax256(float v) {
    __shared__ float sh[8];
    int tid = threadIdx.x;
    #pragma unroll
    for (int o = 16; o; o >>= 1) v = fmaxf(v, __shfl_xor_sync(0xffffffffu, v, o));
    __syncthreads();
    if ((tid & 31) == 0) sh[tid >> 5] = v;
    __syncthreads();
    v = sh[tid & 7];
    #pragma unroll
    for (int o = 4; o; o >>= 1) v = fmaxf(v, __shfl_xor_sync(0xffffffffu, v, o));
    return v;
}

// ---------------- embedding ----------------
__global__ void embed_kernel(const int* __restrict__ ctx,
                             const float* __restrict__ tok,
                             const float* __restrict__ pos) {
    int gid = blockIdx.x * blockDim.x + threadIdx.x;
    int bt = gid >> 10;
    int e  = gid & (E_ - 1);
    int t  = bt & (T_ - 1);
    g_x[gid] = tok[(size_t)ctx[bt] * E_ + e] + pos[t * E_ + e];
}

// ---------------- layernorm -> split bf16 hi/lo planes ----------------
__global__ void ln_split_kernel(const float* __restrict__ in,
                                bf16* __restrict__ hhi, bf16* __restrict__ hlo,
                                const float* __restrict__ g, const float* __restrict__ b) {
    int row = blockIdx.x;
    int tid = threadIdx.x;
    const float4* rp = (const float4*)(in + (size_t)row * E_);
    float4 v = rp[tid];
    float s  = v.x + v.y + v.z + v.w;
    float ss = v.x * v.x + v.y * v.y + v.z * v.z + v.w * v.w;
    s  = blockSum256(s);
    __syncthreads();
    ss = blockSum256(ss);
    float mean = s * (1.0f / E_);
    float var  = ss * (1.0f / E_) - mean * mean;
    float inv  = rsqrtf(var + EPS_);
    int e = tid * 4;
    float o[4];
    o[0] = (v.x - mean) * inv * g[e + 0] + b[e + 0];
    o[1] = (v.y - mean) * inv * g[e + 1] + b[e + 1];
    o[2] = (v.z - mean) * inv * g[e + 2] + b[e + 2];
    o[3] = (v.w - mean) * inv * g[e + 3] + b[e + 3];
    ushort4 ho, lw;
    unsigned short* hp = &ho.x;
    unsigned short* lp = &lw.x;
    #pragma unroll
    for (int j = 0; j < 4; j++) {
        bf16 h = __float2bfloat16(o[j]);
        bf16 l = __float2bfloat16(o[j] - __bfloat162float(h));
        hp[j] = __bfloat16_as_ushort(h);
        lp[j] = __bfloat16_as_ushort(l);
    }
    ((ushort4*)(hhi + (size_t)row * E_))[tid] = ho;
    ((ushort4*)(hlo + (size_t)row * E_))[tid] = lw;
}

// ---------------- weight transpose+split: W[K,N] fp32 -> T[N,K] bf16 hi/lo --------
__global__ void wt_tsplit(const float* __restrict__ W,
                          bf16* __restrict__ Thi, bf16* __restrict__ Tlo,
                          int N, int K) {
    __shared__ float s[32][33];
    int n0 = blockIdx.x * 32;
    int k0 = blockIdx.y * 32;
    int tx = threadIdx.x;   // 0..7
    int ty = threadIdx.y;   // 0..31
    float4 rv = *(const float4*)(W + (size_t)(k0 + ty) * N + n0 + tx * 4);
    s[ty][tx * 4 + 0] = rv.x;
    s[ty][tx * 4 + 1] = rv.y;
    s[ty][tx * 4 + 2] = rv.z;
    s[ty][tx * 4 + 3] = rv.w;
    __syncthreads();
    ushort4 ho, lw;
    unsigned short* hp = &ho.x;
    unsigned short* lp = &lw.x;
    #pragma unroll
    for (int j = 0; j < 4; j++) {
        float f = s[tx * 4 + j][ty];
        bf16 h = __float2bfloat16(f);
        bf16 l = __float2bfloat16(f - __bfloat162float(h));
        hp[j] = __bfloat16_as_ushort(h);
        lp[j] = __bfloat16_as_ushort(l);
    }
    size_t off = (size_t)(n0 + ty) * K + k0 + tx * 4;
    *(ushort4*)(Thi + off) = ho;
    *(ushort4*)(Tlo + off) = lw;
}

// ---------------- V transpose per head: qkv planes -> vt[z*64+d][t] ----------------
__global__ void vt_tsplit_kernel() {
    __shared__ bf16 sh[32][33];
    __shared__ bf16 sl[32][33];
    int z = blockIdx.z;  int b = z >> 4;  int h = z & 15;
    int t0 = blockIdx.x * 32, d0 = blockIdx.y * 32;
    int tx = threadIdx.x, ty = threadIdx.y;
    size_t src = (size_t)(b * T_ + t0 + ty) * (3 * E_) + 2 * E_ + h * HD_ + d0 + tx;
    sh[ty][tx] = g_qkvhi[src];
    sl[ty][tx] = g_qkvlo[src];
    __syncthreads();
    size_t dst = (size_t)(z * HD_ + d0 + ty) * T_ + t0 + tx;
    g_vthi[dst] = sh[tx][ty];
    g_vtlo[dst] = sl[tx][ty];
}

// ============ shared MMA helpers ============
#define MMA16816(c, a, b) \
  asm volatile("mma.sync.aligned.m16n8k16.row.col.f32.bf16.bf16.f32 " \
    "{%0,%1,%2,%3}, {%4,%5,%6,%7}, {%8,%9}, {%0,%1,%2,%3};" \
    : "+f"((c)[0]), "+f"((c)[1]), "+f"((c)[2]), "+f"((c)[3]) \
    : "r"((a)[0]), "r"((a)[1]), "r"((a)[2]), "r"((a)[3]), \
      "r"((b)[0]), "r"((b)[1]))

#define CP16(dst_u32, src) \
  asm volatile("cp.async.cg.shared.global [%0], [%1], 16;" :: "r"(dst_u32), "l"(src))

#define SM_STAGE 20480
#define SM_MAT   5120
#define SM_ROW   40

// ============ general bf16x3 GEMM, 128x128x32, 2-stage cp.async ============
// C = A(MxK) @ Bt(NxK)^T. A planes stride lda, Bt planes stride ldb (k-contiguous).
// Output: fp32 C (+bias+res) or split bf16 planes Chi/Clo (+bias, relu).
__global__ void __launch_bounds__(256) mma_gemm(
        const bf16* __restrict__ Ahi, const bf16* __restrict__ Alo, int lda,
        const bf16* __restrict__ Bthi, const bf16* __restrict__ Btlo, int ldb,
        const float* __restrict__ bias, const float* __restrict__ res,
        float* __restrict__ C, bf16* __restrict__ Chi, bf16* __restrict__ Clo,
        int ldc, int K, int doRelu) {
    extern __shared__ bf16 smem[];

    int tid  = threadIdx.x;
    int warp = tid >> 5, lane = tid & 31;
    int wm = warp & 3;
    int wn = warp >> 2;
    int g  = lane >> 2;
    int tg = lane & 3;

    int row0 = blockIdx.y * 128;
    int col0 = blockIdx.x * 128;

    const bf16* planes[4] = {Ahi, Alo, Bthi, Btlo};
    int lds[4] = {lda, lda, ldb, ldb};
    unsigned smem_u32 = (unsigned)__cvta_generic_to_shared(smem);

    float acc[2][8][4];
    #pragma unroll
    for (int i = 0; i < 2; i++)
        #pragma unroll
        for (int j = 0; j < 8; j++)
            #pragma unroll
            for (int r = 0; r < 4; r++) acc[i][j][r] = 0.0f;

    int nk = K >> 5;

    auto load_stage = [&](int stage, int k0) {
        #pragma unroll
        for (int m = 0; m < 4; m++) {
            const bf16* P = planes[m];
            int base_row = (m < 2) ? row0 : col0;
            int ld = lds[m];
            #pragma unroll
            for (int rep = 0; rep < 2; rep++) {
                int chunk = rep * 256 + tid;
                int row = chunk >> 2;
                int kc  = chunk & 3;
                unsigned dst = smem_u32 +
                    2u * (stage * SM_STAGE + m * SM_MAT + row * SM_ROW + kc * 8);
                const bf16* src = P + (size_t)(base_row + row) * ld + k0 + kc * 8;
                CP16(dst, src);
            }
        }
        asm volatile("cp.async.commit_group;");
    };

    load_stage(0, 0);

    for (int kt = 0; kt < nk; kt++) {
        if (kt + 1 < nk) {
            load_stage((kt + 1) & 1, (kt + 1) << 5);
            asm volatile("cp.async.wait_group 1;");
        } else {
            asm volatile("cp.async.wait_group 0;");
        }
        __syncthreads();

        const bf16* sAhi = smem + (kt & 1) * SM_STAGE;
        const bf16* sAlo = sAhi + SM_MAT;
        const bf16* sBhi = sAhi + 2 * SM_MAT;
        const bf16* sBlo = sAhi + 3 * SM_MAT;

        #pragma unroll
        for (int kk = 0; kk < 32; kk += 16) {
            uint32_t ah[2][4], al[2][4];
            #pragma unroll
            for (int mi = 0; mi < 2; mi++) {
                int r0 = wm * 32 + mi * 16;
                int h0 = kk + tg * 2;
                ah[mi][0] = *(const uint32_t*)(sAhi + (r0 + g    ) * SM_ROW + h0);
                ah[mi][1] = *(const uint32_t*)(sAhi + (r0 + g + 8) * SM_ROW + h0);
                ah[mi][2] = *(const uint32_t*)(sAhi + (r0 + g    ) * SM_ROW + h0 + 8);
                ah[mi][3] = *(const uint32_t*)(sAhi + (r0 + g + 8) * SM_ROW + h0 + 8);
                al[mi][0] = *(const uint32_t*)(sAlo + (r0 + g    ) * SM_ROW + h0);
                al[mi][1] = *(const uint32_t*)(sAlo + (r0 + g + 8) * SM_ROW + h0);
                al[mi][2] = *(const uint32_t*)(sAlo + (r0 + g    ) * SM_ROW + h0 + 8);
                al[mi][3] = *(const uint32_t*)(sAlo + (r0 + g + 8) * SM_ROW + h0 + 8);
            }
            #pragma unroll
            for (int ni = 0; ni < 8; ni++) {
                int c0 = wn * 64 + ni * 8 + g;
                int h0 = kk + tg * 2;
                uint32_t bh[2], bl[2];
                bh[0] = *(const uint32_t*)(sBhi + c0 * SM_ROW + h0);
                bh[1] = *(const uint32_t*)(sBhi + c0 * SM_ROW + h0 + 8);
                bl[0] = *(const uint32_t*)(sBlo + c0 * SM_ROW + h0);
                bl[1] = *(const uint32_t*)(sBlo + c0 * SM_ROW + h0 + 8);
                #pragma unroll
                for (int mi = 0; mi < 2; mi++) {
                    MMA16816(acc[mi][ni], ah[mi], bh);
                    MMA16816(acc[mi][ni], ah[mi], bl);
                    MMA16816(acc[mi][ni], al[mi], bh);
                }
            }
        }
        __syncthreads();
    }

    // ---- epilogue ----
    #pragma unroll
    for (int mi = 0; mi < 2; mi++) {
        int r = row0 + wm * 32 + mi * 16 + g;
        #pragma unroll
        for (int ni = 0; ni < 8; ni++) {
            int c = col0 + wn * 64 + ni * 8 + tg * 2;
            float v0 = acc[mi][ni][0], v1 = acc[mi][ni][1];
            float v2 = acc[mi][ni][2], v3 = acc[mi][ni][3];
            if (bias) {
                float b0 = bias[c], b1 = bias[c + 1];
                v0 += b0; v1 += b1; v2 += b0; v3 += b1;
            }
            if (doRelu) {
                v0 = fmaxf(v0, 0.0f); v1 = fmaxf(v1, 0.0f);
                v2 = fmaxf(v2, 0.0f); v3 = fmaxf(v3, 0.0f);
            }
            if (Chi) {
                float vv[4] = {v0, v1, v2, v3};
                bf16 hh[4], ll[4];
                #pragma unroll
                for (int j = 0; j < 4; j++) {
                    hh[j] = __float2bfloat16(vv[j]);
                    ll[j] = __float2bfloat16(vv[j] - __bfloat162float(hh[j]));
                }
                *(uint32_t*)(Chi + (size_t)r * ldc + c)       = *(uint32_t*)&hh[0];
                *(uint32_t*)(Chi + (size_t)(r + 8) * ldc + c) = *(uint32_t*)&hh[2];
                *(uint32_t*)(Clo + (size_t)r * ldc + c)       = *(uint32_t*)&ll[0];
                *(uint32_t*)(Clo + (size_t)(r + 8) * ldc + c) = *(uint32_t*)&ll[2];
            } else {
                if (res) {
                    v0 += res[(size_t)r * ldc + c];
                    v1 += res[(size_t)r * ldc + c + 1];
                    v2 += res[(size_t)(r + 8) * ldc + c];
                    v3 += res[(size_t)(r + 8) * ldc + c + 1];
                }
                *(float2*)(C + (size_t)r * ldc + c)       = make_float2(v0, v1);
                *(float2*)(C + (size_t)(r + 8) * ldc + c) = make_float2(v2, v3);
            }
        }
    }
}

// ============ tensor-core attention scores: S = scale * Q @ K^T ============
// grid (kt=8, qt=8, z=32); K=64; causal tile skip.
__global__ void __launch_bounds__(256) attn_scores_mma() {
    extern __shared__ bf16 smem[];
    int z = blockIdx.z;
    int qt = blockIdx.y, kt = blockIdx.x;
    if (kt > qt) return;
    int b = z >> 4, h = z & 15;

    const bf16* Ahi = g_qkvhi + (size_t)b * T_ * 3 * E_ + h * HD_;
    const bf16* Alo = g_qkvlo + (size_t)b * T_ * 3 * E_ + h * HD_;
    const bf16* Bhi = g_qkvhi + (size_t)b * T_ * 3 * E_ + E_ + h * HD_;
    const bf16* Blo = g_qkvlo + (size_t)b * T_ * 3 * E_ + E_ + h * HD_;
    const int ld = 3 * E_;
    float* C = g_scores + (size_t)z * T_ * T_;

    int tid  = threadIdx.x;
    int warp = tid >> 5, lane = tid & 31;
    int wm = warp & 3, wn = warp >> 2;
    int g = lane >> 2, tg = lane & 3;
    int row0 = qt * 128, col0 = kt * 128;

    const bf16* planes[4] = {Ahi, Alo, Bhi, Blo};
    unsigned smem_u32 = (unsigned)__cvta_generic_to_shared(smem);

    float acc[2][8][4];
    #pragma unroll
    for (int i = 0; i < 2; i++)
        #pragma unroll
        for (int j = 0; j < 8; j++)
            #pragma unroll
            for (int r = 0; r < 4; r++) acc[i][j][r] = 0.0f;

    auto load_stage = [&](int stage, int k0) {
        #pragma unroll
        for (int m = 0; m < 4; m++) {
            const bf16* P = planes[m];
            int base_row = (m < 2) ? row0 : col0;
            #pragma unroll
            for (int rep = 0; rep < 2; rep++) {
                int chunk = rep * 256 + tid;
                int row = chunk >> 2;
                int kc  = chunk & 3;
                unsigned dst = smem_u32 +
                    2u * (stage * SM_STAGE + m * SM_MAT + row * SM_ROW + kc * 8);
                CP16(dst, P + (size_t)(base_row + row) * ld + k0 + kc * 8);
            }
        }
        asm volatile("cp.async.commit_group;");
    };

    load_stage(0, 0);

    #pragma unroll
    for (int kt2 = 0; kt2 < 2; kt2++) {
        if (kt2 == 0) {
            load_stage(1, 32);
            asm volatile("cp.async.wait_group 1;");
        } else {
            asm volatile("cp.async.wait_group 0;");
        }
        __syncthreads();

        const bf16* sAhi = smem + kt2 * SM_STAGE;
        const bf16* sAlo = sAhi + SM_MAT;
        const bf16* sBhi = sAhi + 2 * SM_MAT;
        const bf16* sBlo = sAhi + 3 * SM_MAT;

        #pragma unroll
        for (int kk = 0; kk < 32; kk += 16) {
            uint32_t ah[2][4], al[2][4];
            #pragma unroll
            for (int mi = 0; mi < 2; mi++) {
                int r0 = wm * 32 + mi * 16;
                int h0 = kk + tg * 2;
                ah[mi][0] = *(const uint32_t*)(sAhi + (r0 + g    ) * SM_ROW + h0);
                ah[mi][1] = *(const uint32_t*)(sAhi + (r0 + g + 8) * SM_ROW + h0);
                ah[mi][2] = *(const uint32_t*)(sAhi + (r0 + g    ) * SM_ROW + h0 + 8);
                ah[mi][3] = *(const uint32_t*)(sAhi + (r0 + g + 8) * SM_ROW + h0 + 8);
                al[mi][0] = *(const uint32_t*)(sAlo + (r0 + g    ) * SM_ROW + h0);
                al[mi][1] = *(const uint32_t*)(sAlo + (r0 + g + 8) * SM_ROW + h0);
                al[mi][2] = *(const uint32_t*)(sAlo + (r0 + g    ) * SM_ROW + h0 + 8);
                al[mi][3] = *(const uint32_t*)(sAlo + (r0 + g + 8) * SM_ROW + h0 + 8);
            }
            #pragma unroll
            for (int ni = 0; ni < 8; ni++) {
                int c0 = wn * 64 + ni * 8 + g;
                int h0 = kk + tg * 2;
                uint32_t bh[2], bl[2];
                bh[0] = *(const uint32_t*)(sBhi + c0 * SM_ROW + h0);
                bh[1] = *(const uint32_t*)(sBhi + c0 * SM_ROW + h0 + 8);
                bl[0] = *(const uint32_t*)(sBlo + c0 * SM_ROW + h0);
                bl[1] = *(const uint32_t*)(sBlo + c0 * SM_ROW + h0 + 8);
                #pragma unroll
                for (int mi = 0; mi < 2; mi++) {
                    MMA16816(acc[mi][ni], ah[mi], bh);
                    MMA16816(acc[mi][ni], ah[mi], bl);
                    MMA16816(acc[mi][ni], al[mi], bh);
                }
            }
        }
        __syncthreads();
    }

    #pragma unroll
    for (int mi = 0; mi < 2; mi++) {
        int r = row0 + wm * 32 + mi * 16 + g;
        #pragma unroll
        for (int ni = 0; ni < 8; ni++) {
            int c = col0 + wn * 64 + ni * 8 + tg * 2;
            *(float2*)(C + (size_t)r * T_ + c) =
                make_float2(acc[mi][ni][0] * SCALE_, acc[mi][ni][1] * SCALE_);
            *(float2*)(C + (size_t)(r + 8) * T_ + c) =
                make_float2(acc[mi][ni][2] * SCALE_, acc[mi][ni][3] * SCALE_);
        }
    }
}

// ---------------- causal row softmax -> split bf16 P planes ----------------
__global__ void softmax_split_kernel() {
    int idx = blockIdx.x;                 // z*T + q
    int q = idx & (T_ - 1);
    const float* row = g_scores + (size_t)idx * T_;
    bf16* ph = g_phi + (size_t)idx * T_;
    bf16* pl = g_plo + (size_t)idx * T_;
    int n = q + 1;
    int tid = threadIdx.x;
    float m = -1e30f;
    for (int i = tid; i < n; i += 256) m = fmaxf(m, row[i]);
    m = blockMax256(m);
    __syncthreads();
    float s = 0.0f;
    for (int i = tid; i < n; i += 256) s += __expf(row[i] - m);
    s = blockSum256(s);
    float inv = 1.0f / s;
    for (int i = tid; i < n; i += 256) {
        float p = __expf(row[i] - m) * inv;
        bf16 h = __float2bfloat16(p);
        ph[i] = h;
        pl[i] = __float2bfloat16(p - __bfloat162float(h));
    }
    bf16 z16 = __float2bfloat16(0.0f);
    for (int i = n + tid; i < T_; i += 256) { ph[i] = z16; pl[i] = z16; }
}

// ============ tensor-core AV: O = P @ V, tile 128x64, causal K bound ============
// grid (1, qt=8, z=32). Warp w: rows w*16..+15, cols 0..63. Output split o planes.
#define AV_A_PLANE 5120
#define AV_B_PLANE 2560
#define AV_STAGE   15360

__global__ void __launch_bounds__(256) attn_av_mma() {
    extern __shared__ bf16 smem[];
    int z = blockIdx.z;
    int qt = blockIdx.y;
    int b = z >> 4, h = z & 15;
    int row0 = qt * 128;

    const bf16* Ahi = g_phi + (size_t)z * T_ * T_;
    const bf16* Alo = g_plo + (size_t)z * T_ * T_;
    const bf16* Bhi = g_vthi + (size_t)z * HD_ * T_;
    const bf16* Blo = g_vtlo + (size_t)z * HD_ * T_;

    int tid  = threadIdx.x;
    int warp = tid >> 5, lane = tid & 31;
    int g = lane >> 2, tg = lane & 3;
    unsigned smem_u32 = (unsigned)__cvta_generic_to_shared(smem);

    float acc[8][4];
    #pragma unroll
    for (int j = 0; j < 8; j++)
        #pragma unroll
        for (int r = 0; r < 4; r++) acc[j][r] = 0.0f;

    int nk = (qt + 1) * 4;   // K = (qt+1)*128, 32 per step

    auto load_stage = [&](int stage, int k0) {
        // A planes: 128 rows x 4 chunks x 2 planes = 1024 chunks
        #pragma unroll
        for (int rep = 0; rep < 4; rep++) {
            int chunk = rep * 256 + tid;
            int plane = chunk >> 9;
            int idx = chunk & 511;
            int row = idx >> 2;
            int kc  = idx & 3;
            unsigned dst = smem_u32 +
                2u * (stage * AV_STAGE + plane * AV_A_PLANE + row * SM_ROW + kc * 8);
            const bf16* P = plane ? Alo : Ahi;
            CP16(dst, P + (size_t)(row0 + row) * T_ + k0 + kc * 8);
        }
        // B planes: 64 rows x 4 chunks x 2 planes = 512 chunks
        #pragma unroll
        for (int rep = 0; rep < 2; rep++) {
            int chunk = rep * 256 + tid;
            int plane = chunk >> 8;
            int idx = chunk & 255;
            int row = idx >> 2;
            int kc  = idx & 3;
            unsigned dst = smem_u32 +
                2u * (stage * AV_STAGE + 2 * AV_A_PLANE + plane * AV_B_PLANE + row * SM_ROW + kc * 8);
            const bf16* P = plane ? Blo : Bhi;
            CP16(dst, P + (size_t)row * T_ + k0 + kc * 8);
        }
        asm volatile("cp.async.commit_group;");
    };

    load_stage(0, 0);

    for (int kt = 0; kt < nk; kt++) {
        if (kt + 1 < nk) {
            load_stage((kt + 1) & 1, (kt + 1) << 5);
            asm volatile("cp.async.wait_group 1;");
        } else {
            asm volatile("cp.async.wait_group 0;");
        }
        __syncthreads();

        const bf16* sAhi = smem + (kt & 1) * AV_STAGE;
        const bf16* sAlo = sAhi + AV_A_PLANE;
        const bf16* sBhi = sAhi + 2 * AV_A_PLANE;
        const bf16* sBlo = sBhi + AV_B_PLANE;

        #pragma unroll
        for (int kk = 0; kk < 32; kk += 16) {
            int r0 = warp * 16;
            int h0 = kk + tg * 2;
            uint32_t ah[4], al[4];
            ah[0] = *(const uint32_t*)(sAhi + (r0 + g    ) * SM_ROW + h0);
            ah[1] = *(const uint32_t*)(sAhi + (r0 + g + 8) * SM_ROW + h0);
            ah[2] = *(const uint32_t*)(sAhi + (r0 + g    ) * SM_ROW + h0 + 8);
            ah[3] = *(const uint32_t*)(sAhi + (r0 + g + 8) * SM_ROW + h0 + 8);
            al[0] = *(const uint32_t*)(sAlo + (r0 + g    ) * SM_ROW + h0);
            al[1] = *(const uint32_t*)(sAlo + (r0 + g + 8) * SM_ROW + h0);
            al[2] = *(const uint32_t*)(sAlo + (r0 + g    ) * SM_ROW + h0 + 8);
            al[3] = *(const uint32_t*)(sAlo + (r0 + g + 8) * SM_ROW + h0 + 8);
            #pragma unroll
            for (int ni = 0; ni < 8; ni++) {
                int c0 = ni * 8 + g;
                uint32_t bh[2], bl[2];
                bh[0] = *(const uint32_t*)(sBhi + c0 * SM_ROW + h0);
                bh[1] = *(const uint32_t*)(sBhi + c0 * SM_ROW + h0 + 8);
                bl[0] = *(const uint32_t*)(sBlo + c0 * SM_ROW + h0);
                bl[1] = *(const uint32_t*)(sBlo + c0 * SM_ROW + h0 + 8);
                MMA16816(acc[ni], ah, bh);
                MMA16816(acc[ni], ah, bl);
                MMA16816(acc[ni], al, bh);
            }
        }
        __syncthreads();
    }

    // epilogue: write split o planes at [b*T + row][h*64 + c]
    int r = b * T_ + row0 + warp * 16 + g;
    #pragma unroll
    for (int ni = 0; ni < 8; ni++) {
        int c = h * HD_ + ni * 8 + tg * 2;
        float vv[4] = {acc[ni][0], acc[ni][1], acc[ni][2], acc[ni][3]};
        bf16 hh[4], ll[4];
        #pragma unroll
        for (int j = 0; j < 4; j++) {
            hh[j] = __float2bfloat16(vv[j]);
            ll[j] = __float2bfloat16(vv[j] - __bfloat162float(hh[j]));
        }
        *(uint32_t*)(g_ohi + (size_t)r * E_ + c)       = *(uint32_t*)&hh[0];
        *(uint32_t*)(g_ohi + (size_t)(r + 8) * E_ + c) = *(uint32_t*)&hh[2];
        *(uint32_t*)(g_olo + (size_t)r * E_ + c)       = *(uint32_t*)&ll[0];
        *(uint32_t*)(g_olo + (size_t)(r + 8) * E_ + c) = *(uint32_t*)&ll[2];
    }
}

// ---------------- loss ----------------
__global__ void rowloss_kernel(const float* __restrict__ logits, const int* __restrict__ tgt) {
    int row = blockIdx.x;
    const float* lr = logits + (size_t)row * V_;
    int tid = threadIdx.x;
    float m = -1e30f;
    for (int i = tid; i < V_; i += 256) m = fmaxf(m, lr[i]);
    m = blockMax256(m);
    __syncthreads();
    float s = 0.0f;
    for (int i = tid; i < V_; i += 256) s += __expf(lr[i] - m);
    s = blockSum256(s);
    if (tid == 0)
        g_rowloss[row] = -(lr[tgt[row]] - m - logf(s));
}

__global__ void loss_final_kernel(float* __restrict__ dst) {
    int tid = threadIdx.x;
    float s = 0.0f;
    for (int i = tid; i < BT_; i += 256) s += g_rowloss[i];
    s = blockSum256(s);
    if (tid == 0) dst[0] = s * (1.0f / BT_);
}

// ---------------- host driver ----------------
#define GEMM_SMEM 81920
#define AV_SMEM   61440

extern "C" void kernel_launch(void* const* d_in, const int* in_sizes, int n_in,
                              void* d_out, int out_size) {
    const int*   context = (const int*)  d_in[0];
    const int*   targets = (const int*)  d_in[1];
    const float* tok_emb = (const float*)d_in[2];
    const float* pos_emb = (const float*)d_in[3];
    const float* Wq    = (const float*)d_in[4];
    const float* Wk    = (const float*)d_in[5];
    const float* Wv    = (const float*)d_in[6];
    const float* Wo    = (const float*)d_in[7];
    const float* bo    = (const float*)d_in[8];
    const float* ln1_g = (const float*)d_in[9];
    const float* ln1_b = (const float*)d_in[10];
    const float* ln2_g = (const float*)d_in[11];
    const float* ln2_b = (const float*)d_in[12];
    const float* W1    = (const float*)d_in[13];
    const float* b1    = (const float*)d_in[14];
    const float* W2    = (const float*)d_in[15];
    const float* b2    = (const float*)d_in[16];
    const float* lnf_g = (const float*)d_in[17];
    const float* lnf_b = (const float*)d_in[18];
    const float* Wlm   = (const float*)d_in[19];
    const float* blm   = (const float*)d_in[20];

    float *x, *logits_sym, *lossdummy;
    bf16 *hhi, *hlo, *qkvhi, *qkvlo, *ffhi, *fflo, *ohi, *olo, *wthi, *wtlo;
    cudaGetSymbolAddress((void**)&x,   g_x);
    cudaGetSymbolAddress((void**)&logits_sym, g_logits);
    cudaGetSymbolAddress((void**)&lossdummy,  g_lossdummy);
    cudaGetSymbolAddress((void**)&hhi, g_hhi);
    cudaGetSymbolAddress((void**)&hlo, g_hlo);
    cudaGetSymbolAddress((void**)&qkvhi, g_qkvhi);
    cudaGetSymbolAddress((void**)&qkvlo, g_qkvlo);
    cudaGetSymbolAddress((void**)&ffhi, g_ffhi);
    cudaGetSymbolAddress((void**)&fflo, g_fflo);
    cudaGetSymbolAddress((void**)&ohi, g_ohi);
    cudaGetSymbolAddress((void**)&olo, g_olo);
    cudaGetSymbolAddress((void**)&wthi, g_wthi);
    cudaGetSymbolAddress((void**)&wtlo, g_wtlo);

    cudaFuncSetAttribute(mma_gemm, cudaFuncAttributeMaxDynamicSharedMemorySize, GEMM_SMEM);
    cudaFuncSetAttribute(attn_scores_mma, cudaFuncAttributeMaxDynamicSharedMemorySize, GEMM_SMEM);
    cudaFuncSetAttribute(attn_av_mma, cudaFuncAttributeMaxDynamicSharedMemorySize, AV_SMEM);

    const long long BTV = (long long)BT_ * V_;
    float* out = (float*)d_out;
    float* logits = ((long long)out_size >= BTV) ? out : logits_sym;
    float* lossdst;
    if ((long long)out_size > BTV)       lossdst = out + BTV;
    else if ((long long)out_size < BTV)  lossdst = out;
    else                                 lossdst = lossdummy;

    embed_kernel<<<(BT_ * E_) / 256, 256>>>(context, tok_emb, pos_emb);

    dim3 gQKV(3 * E_ / 128, BT_ / 128);   // 24 x 16
    dim3 gE(E_ / 128, BT_ / 128);         // 8 x 16
    dim3 gFF(FF_ / 128, BT_ / 128);       // 32 x 16
    dim3 gV2(V_ / 128, BT_ / 128);        // 250 x 16
    dim3 gSc(T_ / 128, T_ / 128, B_ * H_);
    dim3 gAV(1, T_ / 128, B_ * H_);
    dim3 gVT(T_ / 32, HD_ / 32, B_ * H_);
    dim3 tT(8, 32);
    dim3 tVT(32, 32);

    for (int l = 0; l < L_; l++) {
        const float* wq = Wq + (size_t)l * E_ * E_;
        const float* wk = Wk + (size_t)l * E_ * E_;
        const float* wv = Wv + (size_t)l * E_ * E_;
        const float* wo = Wo + (size_t)l * E_ * E_;
        const float* w1 = W1 + (size_t)l * E_ * FF_;
        const float* w2 = W2 + (size_t)l * FF_ * E_;

        // ---- attention block ----
        ln_split_kernel<<<BT_, 256>>>(x, hhi, hlo, ln1_g + l * E_, ln1_b + l * E_);
        wt_tsplit<<<dim3(E_ / 32, E_ / 32), tT>>>(wq, wthi,                         wtlo,                         E_, E_);
        wt_tsplit<<<dim3(E_ / 32, E_ / 32), tT>>>(wk, wthi + (size_t)E_ * E_,       wtlo + (size_t)E_ * E_,       E_, E_);
        wt_tsplit<<<dim3(E_ / 32, E_ / 32), tT>>>(wv, wthi + (size_t)2 * E_ * E_,   wtlo + (size_t)2 * E_ * E_,   E_, E_);
        mma_gemm<<<gQKV, 256, GEMM_SMEM>>>(hhi, hlo, E_, wthi, wtlo, E_,
                                           nullptr, nullptr, nullptr, qkvhi, qkvlo,
                                           3 * E_, E_, 0);
        vt_tsplit_kernel<<<gVT, tVT>>>();
        attn_scores_mma<<<gSc, 256, GEMM_SMEM>>>();
        softmax_split_kernel<<<B_ * H_ * T_, 256>>>();
        attn_av_mma<<<gAV, 256, AV_SMEM>>>();
        wt_tsplit<<<dim3(E_ / 32, E_ / 32), tT>>>(wo, wthi, wtlo, E_, E_);
        mma_gemm<<<gE, 256, GEMM_SMEM>>>(ohi, olo, E_, wthi, wtlo, E_,
                                         bo + l * E_, x, x, nullptr, nullptr,
                                         E_, E_, 0);

        // ---- MLP block ----
        ln_split_kernel<<<BT_, 256>>>(x, hhi, hlo, ln2_g + l * E_, ln2_b + l * E_);
        wt_tsplit<<<dim3(FF_ / 32, E_ / 32), tT>>>(w1, wthi, wtlo, FF_, E_);
        mma_gemm<<<gFF, 256, GEMM_SMEM>>>(hhi, hlo, E_, wthi, wtlo, E_,
                                          b1 + l * FF_, nullptr, nullptr, ffhi, fflo,
                                          FF_, E_, 1);
        wt_tsplit<<<dim3(E_ / 32, FF_ / 32), tT>>>(w2, wthi, wtlo, E_, FF_);
        mma_gemm<<<gE, 256, GEMM_SMEM>>>(ffhi, fflo, FF_, wthi, wtlo, FF_,
                                         b2 + l * E_, x, x, nullptr, nullptr,
                                         E_, FF_, 0);
    }

    // ---- final LN + LM head ----
    ln_split_kernel<<<BT_, 256>>>(x, hhi, hlo, lnf_g, lnf_b);
    wt_tsplit<<<dim3(V_ / 32, E_ / 32), tT>>>(Wlm, wthi, wtlo, V_, E_);
    mma_gemm<<<gV2, 256, GEMM_SMEM>>>(hhi, hlo, E_, wthi, wtlo, E_,
                                      blm, nullptr, logits, nullptr, nullptr,
                                      V_, E_, 0);

    rowloss_kernel<<<BT_, 256>>>(logits, targets);
    loss_final_kernel<<<1, 256>>>(lossdst);
}

// round 9
// speedup vs baseline: 2.4462x; 1.0081x over previous
#include <cuda_runtime.h>
#include <cuda_bf16.h>
#include <stdint.h>
#include <math.h>

// ---------------- problem constants ----------------
#define B_   2
#define T_   1024
#define E_   1024
#define H_   16
#define HD_  64
#define L_   8
#define FF_  4096
#define V_   32000
#define BT_  (B_ * T_)
#define EPS_ 1e-5f
#define SCALE_ 0.03125f   // 1/sqrt(E)

typedef __nv_bfloat16 bf16;

// ---------------- scratch (device globals) ----------------
__device__ float g_x[BT_ * E_];
__device__ float g_scores[(size_t)B_ * H_ * T_ * T_];
__device__ float g_logits[(size_t)BT_ * V_];
__device__ float g_rowloss[BT_];
__device__ float g_lossdummy[4];
__device__ bf16 g_hhi[BT_ * E_];
__device__ bf16 g_hlo[BT_ * E_];
__device__ bf16 g_qkvhi[BT_ * 3 * E_];
__device__ bf16 g_qkvlo[BT_ * 3 * E_];
__device__ bf16 g_vthi[(size_t)B_ * H_ * HD_ * T_];
__device__ bf16 g_vtlo[(size_t)B_ * H_ * HD_ * T_];
__device__ bf16 g_phi[(size_t)B_ * H_ * T_ * T_];
__device__ bf16 g_plo[(size_t)B_ * H_ * T_ * T_];
__device__ bf16 g_ffhi[(size_t)BT_ * FF_];
__device__ bf16 g_fflo[(size_t)BT_ * FF_];
__device__ bf16 g_ohi[BT_ * E_];
__device__ bf16 g_olo[BT_ * E_];
__device__ bf16 g_wthi[(size_t)V_ * E_];
__device__ bf16 g_wtlo[(size_t)V_ * E_];

// ---------------- reductions (blockDim.x == 256) ----------------
__device__ __forceinline__ float blockSum256(float v) {
    __shared__ float sh[8];
    int tid = threadIdx.x;
    #pragma unroll
    for (int o = 16; o; o >>= 1) v += __shfl_xor_sync(0xffffffffu, v, o);
    __syncthreads();
    if ((tid & 31) == 0) sh[tid >> 5] = v;
    __syncthreads();
    v = sh[tid & 7];
    #pragma unroll
    for (int o = 4; o; o >>= 1) v += __shfl_xor_sync(0xffffffffu, v, o);
    return v;
}

__device__ __forceinline__ float blockMax256(float v) {
    __shared__ float sh[8];
    int tid = threadIdx.x;
    #pragma unroll
    for (int o = 16; o; o >>= 1) v = fmaxf(v, __shfl_xor_sync(0xffffffffu, v, o));
    __syncthreads();
    if ((tid & 31) == 0) sh[tid >> 5] = v;
    __syncthreads();
    v = sh[tid & 7];
    #pragma unroll
    for (int o = 4; o; o >>= 1) v = fmaxf(v, __shfl_xor_sync(0xffffffffu, v, o));
    return v;
}

// ---------------- embedding ----------------
__global__ void embed_kernel(const int* __restrict__ ctx,
                             const float* __restrict__ tok,
                             const float* __restrict__ pos) {
    int gid = blockIdx.x * blockDim.x + threadIdx.x;
    int bt = gid >> 10;
    int e  = gid & (E_ - 1);
    int t  = bt & (T_ - 1);
    g_x[gid] = tok[(size_t)ctx[bt] * E_ + e] + pos[t * E_ + e];
}

// ---------------- layernorm -> split bf16 hi/lo planes ----------------
__global__ void ln_split_kernel(const float* __restrict__ in,
                                bf16* __restrict__ hhi, bf16* __restrict__ hlo,
                                const float* __restrict__ g, const float* __restrict__ b) {
    int row = blockIdx.x;
    int tid = threadIdx.x;
    const float4* rp = (const float4*)(in + (size_t)row * E_);
    float4 v = rp[tid];
    float s  = v.x + v.y + v.z + v.w;
    float ss = v.x * v.x + v.y * v.y + v.z * v.z + v.w * v.w;
    s  = blockSum256(s);
    __syncthreads();
    ss = blockSum256(ss);
    float mean = s * (1.0f / E_);
    float var  = ss * (1.0f / E_) - mean * mean;
    float inv  = rsqrtf(var + EPS_);
    int e = tid * 4;
    float o[4];
    o[0] = (v.x - mean) * inv * g[e + 0] + b[e + 0];
    o[1] = (v.y - mean) * inv * g[e + 1] + b[e + 1];
    o[2] = (v.z - mean) * inv * g[e + 2] + b[e + 2];
    o[3] = (v.w - mean) * inv * g[e + 3] + b[e + 3];
    ushort4 ho, lw;
    unsigned short* hp = &ho.x;
    unsigned short* lp = &lw.x;
    #pragma unroll
    for (int j = 0; j < 4; j++) {
        bf16 h = __float2bfloat16(o[j]);
        bf16 l = __float2bfloat16(o[j] - __bfloat162float(h));
        hp[j] = __bfloat16_as_ushort(h);
        lp[j] = __bfloat16_as_ushort(l);
    }
    ((ushort4*)(hhi + (size_t)row * E_))[tid] = ho;
    ((ushort4*)(hlo + (size_t)row * E_))[tid] = lw;
}

// ---------------- weight transpose+split ----------------
__global__ void wt_tsplit(const float* __restrict__ W,
                          bf16* __restrict__ Thi, bf16* __restrict__ Tlo,
                          int N, int K) {
    __shared__ float s[32][33];
    int n0 = blockIdx.x * 32;
    int k0 = blockIdx.y * 32;
    int tx = threadIdx.x;   // 0..7
    int ty = threadIdx.y;   // 0..31
    float4 rv = *(const float4*)(W + (size_t)(k0 + ty) * N + n0 + tx * 4);
    s[ty][tx * 4 + 0] = rv.x;
    s[ty][tx * 4 + 1] = rv.y;
    s[ty][tx * 4 + 2] = rv.z;
    s[ty][tx * 4 + 3] = rv.w;
    __syncthreads();
    ushort4 ho, lw;
    unsigned short* hp = &ho.x;
    unsigned short* lp = &lw.x;
    #pragma unroll
    for (int j = 0; j < 4; j++) {
        float f = s[tx * 4 + j][ty];
        bf16 h = __float2bfloat16(f);
        bf16 l = __float2bfloat16(f - __bfloat162float(h));
        hp[j] = __bfloat16_as_ushort(h);
        lp[j] = __bfloat16_as_ushort(l);
    }
    size_t off = (size_t)(n0 + ty) * K + k0 + tx * 4;
    *(ushort4*)(Thi + off) = ho;
    *(ushort4*)(Tlo + off) = lw;
}

// ---------------- V transpose per head ----------------
__global__ void vt_tsplit_kernel() {
    __shared__ bf16 sh[32][33];
    __shared__ bf16 sl[32][33];
    int z = blockIdx.z;  int b = z >> 4;  int h = z & 15;
    int t0 = blockIdx.x * 32, d0 = blockIdx.y * 32;
    int tx = threadIdx.x, ty = threadIdx.y;
    size_t src = (size_t)(b * T_ + t0 + ty) * (3 * E_) + 2 * E_ + h * HD_ + d0 + tx;
    sh[ty][tx] = g_qkvhi[src];
    sl[ty][tx] = g_qkvlo[src];
    __syncthreads();
    size_t dst = (size_t)(z * HD_ + d0 + ty) * T_ + t0 + tx;
    g_vthi[dst] = sh[tx][ty];
    g_vtlo[dst] = sl[tx][ty];
}

// ============ MMA helpers ============
#define MMA16816(c, a, b) \
  asm volatile("mma.sync.aligned.m16n8k16.row.col.f32.bf16.bf16.f32 " \
    "{%0,%1,%2,%3}, {%4,%5,%6,%7}, {%8,%9}, {%0,%1,%2,%3};" \
    : "+f"((c)[0]), "+f"((c)[1]), "+f"((c)[2]), "+f"((c)[3]) \
    : "r"((a)[0]), "r"((a)[1]), "r"((a)[2]), "r"((a)[3]), \
      "r"((b)[0]), "r"((b)[1]))

#define CP16(dst_u32, src) \
  asm volatile("cp.async.cg.shared.global [%0], [%1], 16;" :: "r"(dst_u32), "l"(src))

__device__ __forceinline__ void ldsm4(uint32_t* r, unsigned a) {
    asm volatile("ldmatrix.sync.aligned.m8n8.x4.shared.b16 {%0,%1,%2,%3}, [%4];"
        : "=r"(r[0]), "=r"(r[1]), "=r"(r[2]), "=r"(r[3]) : "r"(a));
}

#define SM_STAGE 20480          // halves per stage
#define SM_MAT   5120
#define SM_ROW   40
#define SM_STAGE_B 40960u       // bytes per stage
#define SM_MAT_B   10240u
#define SM_TILE_B  1280u        // 16 rows * 40 halves * 2B

// ============ general bf16x3 GEMM, 128x128x32, 3-stage cp.async, ldmatrix ============
__global__ void __launch_bounds__(256) mma_gemm(
        const bf16* __restrict__ Ahi, const bf16* __restrict__ Alo, int lda,
        const bf16* __restrict__ Bthi, const bf16* __restrict__ Btlo, int ldb,
        const float* __restrict__ bias, const float* __restrict__ res,
        float* __restrict__ C, bf16* __restrict__ Chi, bf16* __restrict__ Clo,
        int ldc, int K, int doRelu) {
    extern __shared__ bf16 smem[];

    int tid  = threadIdx.x;
    int warp = tid >> 5, lane = tid & 31;
    int wm = warp & 3;
    int wn = warp >> 2;
    int g  = lane >> 2;
    int tg = lane & 3;
    int t  = lane >> 3, rr = lane & 7;

    int row0 = blockIdx.y * 128;
    int col0 = blockIdx.x * 128;

    const bf16* planes[4] = {Ahi, Alo, Bthi, Btlo};
    int lds[4] = {lda, lda, ldb, ldb};
    unsigned smem_u32 = (unsigned)__cvta_generic_to_shared(smem);

    // ldmatrix per-thread address components (bytes)
    unsigned aoffB = 2u * ((wm * 32 + (t & 1) * 8 + rr) * SM_ROW + (t >> 1) * 8);
    unsigned boffB = 2u * ((wn * 64 + (t >> 1) * 8 + rr) * SM_ROW + (t & 1) * 8);

    float acc[2][8][4];
    #pragma unroll
    for (int i = 0; i < 2; i++)
        #pragma unroll
        for (int j = 0; j < 8; j++)
            #pragma unroll
            for (int r = 0; r < 4; r++) acc[i][j][r] = 0.0f;

    int nk = K >> 5;

    auto load_stage = [&](int stage, int k0) {
        #pragma unroll
        for (int m = 0; m < 4; m++) {
            const bf16* P = planes[m];
            int base_row = (m < 2) ? row0 : col0;
            int ld = lds[m];
            #pragma unroll
            for (int rep = 0; rep < 2; rep++) {
                int chunk = rep * 256 + tid;
                int row = chunk >> 2;
                int kc  = chunk & 3;
                unsigned dst = smem_u32 +
                    2u * (stage * SM_STAGE + m * SM_MAT + row * SM_ROW + kc * 8);
                const bf16* src = P + (size_t)(base_row + row) * ld + k0 + kc * 8;
                CP16(dst, src);
            }
        }
        asm volatile("cp.async.commit_group;");
    };

    load_stage(0, 0);
    if (nk > 1) load_stage(1, 32);

    for (int kt = 0; kt < nk; kt++) {
        if (kt + 1 < nk) { asm volatile("cp.async.wait_group 1;"); }
        else             { asm volatile("cp.async.wait_group 0;"); }
        __syncthreads();

        unsigned sb  = smem_u32 + (unsigned)(kt % 3) * SM_STAGE_B;
        unsigned aHi = sb + aoffB;
        unsigned aLo = aHi + SM_MAT_B;
        unsigned bHi = sb + 2u * SM_MAT_B + boffB;
        unsigned bLo = bHi + SM_MAT_B;

        #pragma unroll
        for (int kk = 0; kk < 32; kk += 16) {
            uint32_t ah[2][4], al[2][4];
            ldsm4(ah[0], aHi + 2 * kk);
            ldsm4(ah[1], aHi + SM_TILE_B + 2 * kk);
            ldsm4(al[0], aLo + 2 * kk);
            ldsm4(al[1], aLo + SM_TILE_B + 2 * kk);
            #pragma unroll
            for (int p = 0; p < 4; p++) {
                uint32_t bh[4], bl[4];
                ldsm4(bh, bHi + p * SM_TILE_B + 2 * kk);
                ldsm4(bl, bLo + p * SM_TILE_B + 2 * kk);
                #pragma unroll
                for (int mi = 0; mi < 2; mi++) {
                    MMA16816(acc[mi][2 * p],     ah[mi], &bh[0]);
                    MMA16816(acc[mi][2 * p],     ah[mi], &bl[0]);
                    MMA16816(acc[mi][2 * p],     al[mi], &bh[0]);
                    MMA16816(acc[mi][2 * p + 1], ah[mi], &bh[2]);
                    MMA16816(acc[mi][2 * p + 1], ah[mi], &bl[2]);
                    MMA16816(acc[mi][2 * p + 1], al[mi], &bh[2]);
                }
            }
        }
        __syncthreads();
        if (kt + 2 < nk) load_stage((kt + 2) % 3, (kt + 2) << 5);
    }

    // ---- epilogue ----
    #pragma unroll
    for (int mi = 0; mi < 2; mi++) {
        int r = row0 + wm * 32 + mi * 16 + g;
        #pragma unroll
        for (int ni = 0; ni < 8; ni++) {
            int c = col0 + wn * 64 + ni * 8 + tg * 2;
            float v0 = acc[mi][ni][0], v1 = acc[mi][ni][1];
            float v2 = acc[mi][ni][2], v3 = acc[mi][ni][3];
            if (bias) {
                float b0 = bias[c], b1 = bias[c + 1];
                v0 += b0; v1 += b1; v2 += b0; v3 += b1;
            }
            if (doRelu) {
                v0 = fmaxf(v0, 0.0f); v1 = fmaxf(v1, 0.0f);
                v2 = fmaxf(v2, 0.0f); v3 = fmaxf(v3, 0.0f);
            }
            if (Chi) {
                float vv[4] = {v0, v1, v2, v3};
                bf16 hh[4], ll[4];
                #pragma unroll
                for (int j = 0; j < 4; j++) {
                    hh[j] = __float2bfloat16(vv[j]);
                    ll[j] = __float2bfloat16(vv[j] - __bfloat162float(hh[j]));
                }
                *(uint32_t*)(Chi + (size_t)r * ldc + c)       = *(uint32_t*)&hh[0];
                *(uint32_t*)(Chi + (size_t)(r + 8) * ldc + c) = *(uint32_t*)&hh[2];
                *(uint32_t*)(Clo + (size_t)r * ldc + c)       = *(uint32_t*)&ll[0];
                *(uint32_t*)(Clo + (size_t)(r + 8) * ldc + c) = *(uint32_t*)&ll[2];
            } else {
                if (res) {
                    v0 += res[(size_t)r * ldc + c];
                    v1 += res[(size_t)r * ldc + c + 1];
                    v2 += res[(size_t)(r + 8) * ldc + c];
                    v3 += res[(size_t)(r + 8) * ldc + c + 1];
                }
                *(float2*)(C + (size_t)r * ldc + c)       = make_float2(v0, v1);
                *(float2*)(C + (size_t)(r + 8) * ldc + c) = make_float2(v2, v3);
            }
        }
    }
}

// ============ attention scores: S = scale * Q @ K^T (2-stage, ldmatrix) ============
__global__ void __launch_bounds__(256) attn_scores_mma() {
    extern __shared__ bf16 smem[];
    int z = blockIdx.z;
    int qt = blockIdx.y, kt = blockIdx.x;
    if (kt > qt) return;
    int b = z >> 4, h = z & 15;

    const bf16* Ahi = g_qkvhi + (size_t)b * T_ * 3 * E_ + h * HD_;
    const bf16* Alo = g_qkvlo + (size_t)b * T_ * 3 * E_ + h * HD_;
    const bf16* Bhi = g_qkvhi + (size_t)b * T_ * 3 * E_ + E_ + h * HD_;
    const bf16* Blo = g_qkvlo + (size_t)b * T_ * 3 * E_ + E_ + h * HD_;
    const int ld = 3 * E_;
    float* C = g_scores + (size_t)z * T_ * T_;

    int tid  = threadIdx.x;
    int warp = tid >> 5, lane = tid & 31;
    int wm = warp & 3, wn = warp >> 2;
    int g = lane >> 2, tg = lane & 3;
    int t = lane >> 3, rr = lane & 7;
    int row0 = qt * 128, col0 = kt * 128;

    const bf16* planes[4] = {Ahi, Alo, Bhi, Blo};
    unsigned smem_u32 = (unsigned)__cvta_generic_to_shared(smem);
    unsigned aoffB = 2u * ((wm * 32 + (t & 1) * 8 + rr) * SM_ROW + (t >> 1) * 8);
    unsigned boffB = 2u * ((wn * 64 + (t >> 1) * 8 + rr) * SM_ROW + (t & 1) * 8);

    float acc[2][8][4];
    #pragma unroll
    for (int i = 0; i < 2; i++)
        #pragma unroll
        for (int j = 0; j < 8; j++)
            #pragma unroll
            for (int r = 0; r < 4; r++) acc[i][j][r] = 0.0f;

    auto load_stage = [&](int stage, int k0) {
        #pragma unroll
        for (int m = 0; m < 4; m++) {
            const bf16* P = planes[m];
            int base_row = (m < 2) ? row0 : col0;
            #pragma unroll
            for (int rep = 0; rep < 2; rep++) {
                int chunk = rep * 256 + tid;
                int row = chunk >> 2;
                int kc  = chunk & 3;
                unsigned dst = smem_u32 +
                    2u * (stage * SM_STAGE + m * SM_MAT + row * SM_ROW + kc * 8);
                CP16(dst, P + (size_t)(base_row + row) * ld + k0 + kc * 8);
            }
        }
        asm volatile("cp.async.commit_group;");
    };

    load_stage(0, 0);

    #pragma unroll
    for (int kt2 = 0; kt2 < 2; kt2++) {
        if (kt2 == 0) {
            load_stage(1, 32);
            asm volatile("cp.async.wait_group 1;");
        } else {
            asm volatile("cp.async.wait_group 0;");
        }
        __syncthreads();

        unsigned sb  = smem_u32 + (unsigned)kt2 * SM_STAGE_B;
        unsigned aHi = sb + aoffB;
        unsigned aLo = aHi + SM_MAT_B;
        unsigned bHi = sb + 2u * SM_MAT_B + boffB;
        unsigned bLo = bHi + SM_MAT_B;

        #pragma unroll
        for (int kk = 0; kk < 32; kk += 16) {
            uint32_t ah[2][4], al[2][4];
            ldsm4(ah[0], aHi + 2 * kk);
            ldsm4(ah[1], aHi + SM_TILE_B + 2 * kk);
            ldsm4(al[0], aLo + 2 * kk);
            ldsm4(al[1], aLo + SM_TILE_B + 2 * kk);
            #pragma unroll
            for (int p = 0; p < 4; p++) {
                uint32_t bh[4], bl[4];
                ldsm4(bh, bHi + p * SM_TILE_B + 2 * kk);
                ldsm4(bl, bLo + p * SM_TILE_B + 2 * kk);
                #pragma unroll
                for (int mi = 0; mi < 2; mi++) {
                    MMA16816(acc[mi][2 * p],     ah[mi], &bh[0]);
                    MMA16816(acc[mi][2 * p],     ah[mi], &bl[0]);
                    MMA16816(acc[mi][2 * p],     al[mi], &bh[0]);
                    MMA16816(acc[mi][2 * p + 1], ah[mi], &bh[2]);
                    MMA16816(acc[mi][2 * p + 1], ah[mi], &bl[2]);
                    MMA16816(acc[mi][2 * p + 1], al[mi], &bh[2]);
                }
            }
        }
        __syncthreads();
    }

    #pragma unroll
    for (int mi = 0; mi < 2; mi++) {
        int r = row0 + wm * 32 + mi * 16 + g;
        #pragma unroll
        for (int ni = 0; ni < 8; ni++) {
            int c = col0 + wn * 64 + ni * 8 + tg * 2;
            *(float2*)(C + (size_t)r * T_ + c) =
                make_float2(acc[mi][ni][0] * SCALE_, acc[mi][ni][1] * SCALE_);
            *(float2*)(C + (size_t)(r + 8) * T_ + c) =
                make_float2(acc[mi][ni][2] * SCALE_, acc[mi][ni][3] * SCALE_);
        }
    }
}

// ---------------- causal row softmax -> split bf16 P planes ----------------
__global__ void softmax_split_kernel() {
    int idx = blockIdx.x;
    int q = idx & (T_ - 1);
    const float* row = g_scores + (size_t)idx * T_;
    bf16* ph = g_phi + (size_t)idx * T_;
    bf16* pl = g_plo + (size_t)idx * T_;
    int n = q + 1;
    int tid = threadIdx.x;
    float m = -1e30f;
    for (int i = tid; i < n; i += 256) m = fmaxf(m, row[i]);
    m = blockMax256(m);
    __syncthreads();
    float s = 0.0f;
    for (int i = tid; i < n; i += 256) s += __expf(row[i] - m);
    s = blockSum256(s);
    float inv = 1.0f / s;
    for (int i = tid; i < n; i += 256) {
        float p = __expf(row[i] - m) * inv;
        bf16 h = __float2bfloat16(p);
        ph[i] = h;
        pl[i] = __float2bfloat16(p - __bfloat162float(h));
    }
    bf16 z16 = __float2bfloat16(0.0f);
    for (int i = n + tid; i < T_; i += 256) { ph[i] = z16; pl[i] = z16; }
}

// ============ AV: O = P @ V, 128x64 tile, causal K bound, ldmatrix ============
#define AV_A_PLANE 5120
#define AV_B_PLANE 2560
#define AV_STAGE   15360
#define AV_STAGE_B 30720u

__global__ void __launch_bounds__(256) attn_av_mma() {
    extern __shared__ bf16 smem[];
    int z = blockIdx.z;
    int qt = blockIdx.y;
    int b = z >> 4, h = z & 15;
    int row0 = qt * 128;

    const bf16* Ahi = g_phi + (size_t)z * T_ * T_;
    const bf16* Alo = g_plo + (size_t)z * T_ * T_;
    const bf16* Bhi = g_vthi + (size_t)z * HD_ * T_;
    const bf16* Blo = g_vtlo + (size_t)z * HD_ * T_;

    int tid  = threadIdx.x;
    int warp = tid >> 5, lane = tid & 31;
    int g = lane >> 2, tg = lane & 3;
    int t = lane >> 3, rr = lane & 7;
    unsigned smem_u32 = (unsigned)__cvta_generic_to_shared(smem);
    unsigned aoffB = 2u * ((warp * 16 + (t & 1) * 8 + rr) * SM_ROW + (t >> 1) * 8);
    unsigned boffB = 2u * (((t >> 1) * 8 + rr) * SM_ROW + (t & 1) * 8);

    float acc[8][4];
    #pragma unroll
    for (int j = 0; j < 8; j++)
        #pragma unroll
        for (int r = 0; r < 4; r++) acc[j][r] = 0.0f;

    int nk = (qt + 1) * 4;

    auto load_stage = [&](int stage, int k0) {
        #pragma unroll
        for (int rep = 0; rep < 4; rep++) {
            int chunk = rep * 256 + tid;
            int plane = chunk >> 9;
            int idx = chunk & 511;
            int row = idx >> 2;
            int kc  = idx & 3;
            unsigned dst = smem_u32 +
                2u * (stage * AV_STAGE + plane * AV_A_PLANE + row * SM_ROW + kc * 8);
            const bf16* P = plane ? Alo : Ahi;
            CP16(dst, P + (size_t)(row0 + row) * T_ + k0 + kc * 8);
        }
        #pragma unroll
        for (int rep = 0; rep < 2; rep++) {
            int chunk = rep * 256 + tid;
            int plane = chunk >> 8;
            int idx = chunk & 255;
            int row = idx >> 2;
            int kc  = idx & 3;
            unsigned dst = smem_u32 +
                2u * (stage * AV_STAGE + 2 * AV_A_PLANE + plane * AV_B_PLANE + row * SM_ROW + kc * 8);
            const bf16* P = plane ? Blo : Bhi;
            CP16(dst, P + (size_t)row * T_ + k0 + kc * 8);
        }
        asm volatile("cp.async.commit_group;");
    };

    load_stage(0, 0);

    for (int kt = 0; kt < nk; kt++) {
        if (kt + 1 < nk) {
            load_stage((kt + 1) & 1, (kt + 1) << 5);
            asm volatile("cp.async.wait_group 1;");
        } else {
            asm volatile("cp.async.wait_group 0;");
        }
        __syncthreads();

        unsigned sb  = smem_u32 + (unsigned)(kt & 1) * AV_STAGE_B;
        unsigned aHi = sb + aoffB;
        unsigned aLo = aHi + 2u * AV_A_PLANE;   // bytes: plane stride = 5120 halves = 10240B
        unsigned bHi = sb + 4u * AV_A_PLANE + boffB;
        unsigned bLo = bHi + 2u * AV_B_PLANE;

        #pragma unroll
        for (int kk = 0; kk < 32; kk += 16) {
            uint32_t ah[4], al[4];
            ldsm4(ah, aHi + 2 * kk);
            ldsm4(al, aLo + 2 * kk);
            #pragma unroll
            for (int p = 0; p < 4; p++) {
                uint32_t bh[4], bl[4];
                ldsm4(bh, bHi + p * SM_TILE_B + 2 * kk);
                ldsm4(bl, bLo + p * SM_TILE_B + 2 * kk);
                MMA16816(acc[2 * p],     ah, &bh[0]);
                MMA16816(acc[2 * p],     ah, &bl[0]);
                MMA16816(acc[2 * p],     al, &bh[0]);
                MMA16816(acc[2 * p + 1], ah, &bh[2]);
                MMA16816(acc[2 * p + 1], ah, &bl[2]);
                MMA16816(acc[2 * p + 1], al, &bh[2]);
            }
        }
        __syncthreads();
    }

    int r = b * T_ + row0 + warp * 16 + g;
    #pragma unroll
    for (int ni = 0; ni < 8; ni++) {
        int c = h * HD_ + ni * 8 + tg * 2;
        float vv[4] = {acc[ni][0], acc[ni][1], acc[ni][2], acc[ni][3]};
        bf16 hh[4], ll[4];
        #pragma unroll
        for (int j = 0; j < 4; j++) {
            hh[j] = __float2bfloat16(vv[j]);
            ll[j] = __float2bfloat16(vv[j] - __bfloat162float(hh[j]));
        }
        *(uint32_t*)(g_ohi + (size_t)r * E_ + c)       = *(uint32_t*)&hh[0];
        *(uint32_t*)(g_ohi + (size_t)(r + 8) * E_ + c) = *(uint32_t*)&hh[2];
        *(uint32_t*)(g_olo + (size_t)r * E_ + c)       = *(uint32_t*)&ll[0];
        *(uint32_t*)(g_olo + (size_t)(r + 8) * E_ + c) = *(uint32_t*)&ll[2];
    }
}

// ---------------- loss ----------------
__global__ void rowloss_kernel(const float* __restrict__ logits, const int* __restrict__ tgt) {
    int row = blockIdx.x;
    const float* lr = logits + (size_t)row * V_;
    int tid = threadIdx.x;
    float m = -1e30f;
    for (int i = tid; i < V_; i += 256) m = fmaxf(m, lr[i]);
    m = blockMax256(m);
    __syncthreads();
    float s = 0.0f;
    for (int i = tid; i < V_; i += 256) s += __expf(lr[i] - m);
    s = blockSum256(s);
    if (tid == 0)
        g_rowloss[row] = -(lr[tgt[row]] - m - logf(s));
}

__global__ void loss_final_kernel(float* __restrict__ dst) {
    int tid = threadIdx.x;
    float s = 0.0f;
    for (int i = tid; i < BT_; i += 256) s += g_rowloss[i];
    s = blockSum256(s);
    if (tid == 0) dst[0] = s * (1.0f / BT_);
}

// ---------------- host driver ----------------
#define GEMM_SMEM 122880
#define SC_SMEM   81920
#define AV_SMEM   61440

extern "C" void kernel_launch(void* const* d_in, const int* in_sizes, int n_in,
                              void* d_out, int out_size) {
    const int*   context = (const int*)  d_in[0];
    const int*   targets = (const int*)  d_in[1];
    const float* tok_emb = (const float*)d_in[2];
    const float* pos_emb = (const float*)d_in[3];
    const float* Wq    = (const float*)d_in[4];
    const float* Wk    = (const float*)d_in[5];
    const float* Wv    = (const float*)d_in[6];
    const float* Wo    = (const float*)d_in[7];
    const float* bo    = (const float*)d_in[8];
    const float* ln1_g = (const float*)d_in[9];
    const float* ln1_b = (const float*)d_in[10];
    const float* ln2_g = (const float*)d_in[11];
    const float* ln2_b = (const float*)d_in[12];
    const float* W1    = (const float*)d_in[13];
    const float* b1    = (const float*)d_in[14];
    const float* W2    = (const float*)d_in[15];
    const float* b2    = (const float*)d_in[16];
    const float* lnf_g = (const float*)d_in[17];
    const float* lnf_b = (const float*)d_in[18];
    const float* Wlm   = (const float*)d_in[19];
    const float* blm   = (const float*)d_in[20];

    float *x, *logits_sym, *lossdummy;
    bf16 *hhi, *hlo, *qkvhi, *qkvlo, *ffhi, *fflo, *ohi, *olo, *wthi, *wtlo;
    cudaGetSymbolAddress((void**)&x,   g_x);
    cudaGetSymbolAddress((void**)&logits_sym, g_logits);
    cudaGetSymbolAddress((void**)&lossdummy,  g_lossdummy);
    cudaGetSymbolAddress((void**)&hhi, g_hhi);
    cudaGetSymbolAddress((void**)&hlo, g_hlo);
    cudaGetSymbolAddress((void**)&qkvhi, g_qkvhi);
    cudaGetSymbolAddress((void**)&qkvlo, g_qkvlo);
    cudaGetSymbolAddress((void**)&ffhi, g_ffhi);
    cudaGetSymbolAddress((void**)&fflo, g_fflo);
    cudaGetSymbolAddress((void**)&ohi, g_ohi);
    cudaGetSymbolAddress((void**)&olo, g_olo);
    cudaGetSymbolAddress((void**)&wthi, g_wthi);
    cudaGetSymbolAddress((void**)&wtlo, g_wtlo);

    cudaFuncSetAttribute(mma_gemm, cudaFuncAttributeMaxDynamicSharedMemorySize, GEMM_SMEM);
    cudaFuncSetAttribute(attn_scores_mma, cudaFuncAttributeMaxDynamicSharedMemorySize, SC_SMEM);
    cudaFuncSetAttribute(attn_av_mma, cudaFuncAttributeMaxDynamicSharedMemorySize, AV_SMEM);

    const long long BTV = (long long)BT_ * V_;
    float* out = (float*)d_out;
    float* logits = ((long long)out_size >= BTV) ? out : logits_sym;
    float* lossdst;
    if ((long long)out_size > BTV)       lossdst = out + BTV;
    else if ((long long)out_size < BTV)  lossdst = out;
    else                                 lossdst = lossdummy;

    embed_kernel<<<(BT_ * E_) / 256, 256>>>(context, tok_emb, pos_emb);

    dim3 gQKV(3 * E_ / 128, BT_ / 128);
    dim3 gE(E_ / 128, BT_ / 128);
    dim3 gFF(FF_ / 128, BT_ / 128);
    dim3 gV2(V_ / 128, BT_ / 128);
    dim3 gSc(T_ / 128, T_ / 128, B_ * H_);
    dim3 gAV(1, T_ / 128, B_ * H_);
    dim3 gVT(T_ / 32, HD_ / 32, B_ * H_);
    dim3 tT(8, 32);
    dim3 tVT(32, 32);

    for (int l = 0; l < L_; l++) {
        const float* wq = Wq + (size_t)l * E_ * E_;
        const float* wk = Wk + (size_t)l * E_ * E_;
        const float* wv = Wv + (size_t)l * E_ * E_;
        const float* wo = Wo + (size_t)l * E_ * E_;
        const float* w1 = W1 + (size_t)l * E_ * FF_;
        const float* w2 = W2 + (size_t)l * FF_ * E_;

        // ---- attention block ----
        ln_split_kernel<<<BT_, 256>>>(x, hhi, hlo, ln1_g + l * E_, ln1_b + l * E_);
        wt_tsplit<<<dim3(E_ / 32, E_ / 32), tT>>>(wq, wthi,                       wtlo,                       E_, E_);
        wt_tsplit<<<dim3(E_ / 32, E_ / 32), tT>>>(wk, wthi + (size_t)E_ * E_,     wtlo + (size_t)E_ * E_,     E_, E_);
        wt_tsplit<<<dim3(E_ / 32, E_ / 32), tT>>>(wv, wthi + (size_t)2 * E_ * E_, wtlo + (size_t)2 * E_ * E_, E_, E_);
        mma_gemm<<<gQKV, 256, GEMM_SMEM>>>(hhi, hlo, E_, wthi, wtlo, E_,
                                           nullptr, nullptr, nullptr, qkvhi, qkvlo,
                                           3 * E_, E_, 0);
        vt_tsplit_kernel<<<gVT, tVT>>>();
        attn_scores_mma<<<gSc, 256, SC_SMEM>>>();
        softmax_split_kernel<<<B_ * H_ * T_, 256>>>();
        attn_av_mma<<<gAV, 256, AV_SMEM>>>();
        wt_tsplit<<<dim3(E_ / 32, E_ / 32), tT>>>(wo, wthi, wtlo, E_, E_);
        mma_gemm<<<gE, 256, GEMM_SMEM>>>(ohi, olo, E_, wthi, wtlo, E_,
                                         bo + l * E_, x, x, nullptr, nullptr,
                                         E_, E_, 0);

        // ---- MLP block ----
        ln_split_kernel<<<BT_, 256>>>(x, hhi, hlo, ln2_g + l * E_, ln2_b + l * E_);
        wt_tsplit<<<dim3(FF_ / 32, E_ / 32), tT>>>(w1, wthi, wtlo, FF_, E_);
        mma_gemm<<<gFF, 256, GEMM_SMEM>>>(hhi, hlo, E_, wthi, wtlo, E_,
                                          b1 + l * FF_, nullptr, nullptr, ffhi, fflo,
                                          FF_, E_, 1);
        wt_tsplit<<<dim3(E_ / 32, FF_ / 32), tT>>>(w2, wthi, wtlo, E_, FF_);
        mma_gemm<<<gE, 256, GEMM_SMEM>>>(ffhi, fflo, FF_, wthi, wtlo, FF_,
                                         b2 + l * E_, x, x, nullptr, nullptr,
                                         E_, FF_, 0);
    }

    // ---- final LN + LM head ----
    ln_split_kernel<<<BT_, 256>>>(x, hhi, hlo, lnf_g, lnf_b);
    wt_tsplit<<<dim3(V_ / 32, E_ / 32), tT>>>(Wlm, wthi, wtlo, V_, E_);
    mma_gemm<<<gV2, 256, GEMM_SMEM>>>(hhi, hlo, E_, wthi, wtlo, E_,
                                      blm, nullptr, logits, nullptr, nullptr,
                                      V_, E_, 0);

    rowloss_kernel<<<BT_, 256>>>(logits, targets);
    loss_final_kernel<<<1, 256>>>(lossdst);
}

// round 11
// speedup vs baseline: 2.5358x; 1.0366x over previous
#include <cuda_runtime.h>
#include <cuda_bf16.h>
#include <stdint.h>
#include <math.h>

// ---------------- problem constants ----------------
#define B_   2
#define T_   1024
#define E_   1024
#define H_   16
#define HD_  64
#define L_   8
#define FF_  4096
#define V_   32000
#define BT_  (B_ * T_)
#define EPS_ 1e-5f
#define SCALE_ 0.03125f   // 1/sqrt(E)

typedef __nv_bfloat16 bf16;

// ---------------- scratch (device globals) ----------------
__device__ float g_x[BT_ * E_];
__device__ float g_scores[(size_t)B_ * H_ * T_ * T_];
__device__ float g_logits[(size_t)BT_ * V_];
__device__ float g_rowloss[BT_];
__device__ float g_lossdummy[4];
__device__ bf16 g_hhi[BT_ * E_];
__device__ bf16 g_hlo[BT_ * E_];
__device__ bf16 g_qkvhi[BT_ * 3 * E_];
__device__ bf16 g_qkvlo[BT_ * 3 * E_];
__device__ bf16 g_vthi[(size_t)B_ * H_ * HD_ * T_];
__device__ bf16 g_vtlo[(size_t)B_ * H_ * HD_ * T_];
__device__ bf16 g_phi[(size_t)B_ * H_ * T_ * T_];
__device__ bf16 g_plo[(size_t)B_ * H_ * T_ * T_];
__device__ bf16 g_ffhi[(size_t)BT_ * FF_];
__device__ bf16 g_fflo[(size_t)BT_ * FF_];
__device__ bf16 g_ohi[BT_ * E_];
__device__ bf16 g_olo[BT_ * E_];
__device__ bf16 g_wthi[(size_t)V_ * E_];
__device__ bf16 g_wtlo[(size_t)V_ * E_];

// ---------------- reductions (blockDim.x == 256) ----------------
__device__ __forceinline__ float blockSum256(float v) {
    __shared__ float sh[8];
    int tid = threadIdx.x;
    #pragma unroll
    for (int o = 16; o; o >>= 1) v += __shfl_xor_sync(0xffffffffu, v, o);
    __syncthreads();
    if ((tid & 31) == 0) sh[tid >> 5] = v;
    __syncthreads();
    v = sh[tid & 7];
    #pragma unroll
    for (int o = 4; o; o >>= 1) v += __shfl_xor_sync(0xffffffffu, v, o);
    return v;
}

__device__ __forceinline__ float blockMax256(float v) {
    __shared__ float sh[8];
    int tid = threadIdx.x;
    #pragma unroll
    for (int o = 16; o; o >>= 1) v = fmaxf(v, __shfl_xor_sync(0xffffffffu, v, o));
    __syncthreads();
    if ((tid & 31) == 0) sh[tid >> 5] = v;
    __syncthreads();
    v = sh[tid & 7];
    #pragma unroll
    for (int o = 4; o; o >>= 1) v = fmaxf(v, __shfl_xor_sync(0xffffffffu, v, o));
    return v;
}

// ---------------- embedding ----------------
__global__ void embed_kernel(const int* __restrict__ ctx,
                             const float* __restrict__ tok,
                             const float* __restrict__ pos) {
    int gid = blockIdx.x * blockDim.x + threadIdx.x;
    int bt = gid >> 10;
    int e  = gid & (E_ - 1);
    int t  = bt & (T_ - 1);
    g_x[gid] = tok[(size_t)ctx[bt] * E_ + e] + pos[t * E_ + e];
}

// ---------------- layernorm -> split bf16 hi/lo planes ----------------
__global__ void ln_split_kernel(const float* __restrict__ in,
                                bf16* __restrict__ hhi, bf16* __restrict__ hlo,
                                const float* __restrict__ g, const float* __restrict__ b) {
    int row = blockIdx.x;
    int tid = threadIdx.x;
    const float4* rp = (const float4*)(in + (size_t)row * E_);
    float4 v = rp[tid];
    float s  = v.x + v.y + v.z + v.w;
    float ss = v.x * v.x + v.y * v.y + v.z * v.z + v.w * v.w;
    s  = blockSum256(s);
    __syncthreads();
    ss = blockSum256(ss);
    float mean = s * (1.0f / E_);
    float var  = ss * (1.0f / E_) - mean * mean;
    float inv  = rsqrtf(var + EPS_);
    int e = tid * 4;
    float o[4];
    o[0] = (v.x - mean) * inv * g[e + 0] + b[e + 0];
    o[1] = (v.y - mean) * inv * g[e + 1] + b[e + 1];
    o[2] = (v.z - mean) * inv * g[e + 2] + b[e + 2];
    o[3] = (v.w - mean) * inv * g[e + 3] + b[e + 3];
    ushort4 ho, lw;
    unsigned short* hp = &ho.x;
    unsigned short* lp = &lw.x;
    #pragma unroll
    for (int j = 0; j < 4; j++) {
        bf16 h = __float2bfloat16(o[j]);
        bf16 l = __float2bfloat16(o[j] - __bfloat162float(h));
        hp[j] = __bfloat16_as_ushort(h);
        lp[j] = __bfloat16_as_ushort(l);
    }
    ((ushort4*)(hhi + (size_t)row * E_))[tid] = ho;
    ((ushort4*)(hlo + (size_t)row * E_))[tid] = lw;
}

// ---------------- weight transpose+split ----------------
__global__ void wt_tsplit(const float* __restrict__ W,
                          bf16* __restrict__ Thi, bf16* __restrict__ Tlo,
                          int N, int K) {
    __shared__ float s[32][33];
    int n0 = blockIdx.x * 32;
    int k0 = blockIdx.y * 32;
    int tx = threadIdx.x;   // 0..7
    int ty = threadIdx.y;   // 0..31
    float4 rv = *(const float4*)(W + (size_t)(k0 + ty) * N + n0 + tx * 4);
    s[ty][tx * 4 + 0] = rv.x;
    s[ty][tx * 4 + 1] = rv.y;
    s[ty][tx * 4 + 2] = rv.z;
    s[ty][tx * 4 + 3] = rv.w;
    __syncthreads();
    ushort4 ho, lw;
    unsigned short* hp = &ho.x;
    unsigned short* lp = &lw.x;
    #pragma unroll
    for (int j = 0; j < 4; j++) {
        float f = s[tx * 4 + j][ty];
        bf16 h = __float2bfloat16(f);
        bf16 l = __float2bfloat16(f - __bfloat162float(h));
        hp[j] = __bfloat16_as_ushort(h);
        lp[j] = __bfloat16_as_ushort(l);
    }
    size_t off = (size_t)(n0 + ty) * K + k0 + tx * 4;
    *(ushort4*)(Thi + off) = ho;
    *(ushort4*)(Tlo + off) = lw;
}

// ---------------- V transpose per head ----------------
__global__ void vt_tsplit_kernel() {
    __shared__ bf16 sh[32][33];
    __shared__ bf16 sl[32][33];
    int z = blockIdx.z;  int b = z >> 4;  int h = z & 15;
    int t0 = blockIdx.x * 32, d0 = blockIdx.y * 32;
    int tx = threadIdx.x, ty = threadIdx.y;
    size_t src = (size_t)(b * T_ + t0 + ty) * (3 * E_) + 2 * E_ + h * HD_ + d0 + tx;
    sh[ty][tx] = g_qkvhi[src];
    sl[ty][tx] = g_qkvlo[src];
    __syncthreads();
    size_t dst = (size_t)(z * HD_ + d0 + ty) * T_ + t0 + tx;
    g_vthi[dst] = sh[tx][ty];
    g_vtlo[dst] = sl[tx][ty];
}

// ============ MMA helpers ============
#define MMA16816(c, a, b) \
  asm volatile("mma.sync.aligned.m16n8k16.row.col.f32.bf16.bf16.f32 " \
    "{%0,%1,%2,%3}, {%4,%5,%6,%7}, {%8,%9}, {%0,%1,%2,%3};" \
    : "+f"((c)[0]), "+f"((c)[1]), "+f"((c)[2]), "+f"((c)[3]) \
    : "r"((a)[0]), "r"((a)[1]), "r"((a)[2]), "r"((a)[3]), \
      "r"((b)[0]), "r"((b)[1]))

#define CP16(dst_u32, src) \
  asm volatile("cp.async.cg.shared.global [%0], [%1], 16;" :: "r"(dst_u32), "l"(src))

__device__ __forceinline__ void ldsm4(uint32_t* r, unsigned a) {
    asm volatile("ldmatrix.sync.aligned.m8n8.x4.shared.b16 {%0,%1,%2,%3}, [%4];"
        : "=r"(r[0]), "=r"(r[1]), "=r"(r[2]), "=r"(r[3]) : "r"(a));
}

#define SM_STAGE 20480          // halves per stage
#define SM_MAT   5120
#define SM_ROW   40
#define SM_STAGE_B 40960u       // bytes per stage
#define SM_MAT_B   10240u
#define SM_TILE_B  1280u        // 16 rows * 40 halves * 2B

// ============ general bf16x3 GEMM, 128x128x32, 3-stage cp.async, ldmatrix ============
// Inner loop is TERM-MAJOR: all accumulators touched once per term -> RAW chain
// distance 16 instead of 1.
__global__ void __launch_bounds__(256, 1) mma_gemm(
        const bf16* __restrict__ Ahi, const bf16* __restrict__ Alo, int lda,
        const bf16* __restrict__ Bthi, const bf16* __restrict__ Btlo, int ldb,
        const float* __restrict__ bias, const float* __restrict__ res,
        float* __restrict__ C, bf16* __restrict__ Chi, bf16* __restrict__ Clo,
        int ldc, int K, int doRelu) {
    extern __shared__ bf16 smem[];

    int tid  = threadIdx.x;
    int warp = tid >> 5, lane = tid & 31;
    int wm = warp & 3;
    int wn = warp >> 2;
    int g  = lane >> 2;
    int tg = lane & 3;
    int t  = lane >> 3, rr = lane & 7;

    int row0 = blockIdx.y * 128;
    int col0 = blockIdx.x * 128;

    const bf16* planes[4] = {Ahi, Alo, Bthi, Btlo};
    int lds[4] = {lda, lda, ldb, ldb};
    unsigned smem_u32 = (unsigned)__cvta_generic_to_shared(smem);

    unsigned aoffB = 2u * ((wm * 32 + (t & 1) * 8 + rr) * SM_ROW + (t >> 1) * 8);
    unsigned boffB = 2u * ((wn * 64 + (t >> 1) * 8 + rr) * SM_ROW + (t & 1) * 8);

    float acc[2][8][4];
    #pragma unroll
    for (int i = 0; i < 2; i++)
        #pragma unroll
        for (int j = 0; j < 8; j++)
            #pragma unroll
            for (int r = 0; r < 4; r++) acc[i][j][r] = 0.0f;

    int nk = K >> 5;

    auto load_stage = [&](int stage, int k0) {
        #pragma unroll
        for (int m = 0; m < 4; m++) {
            const bf16* P = planes[m];
            int base_row = (m < 2) ? row0 : col0;
            int ld = lds[m];
            #pragma unroll
            for (int rep = 0; rep < 2; rep++) {
                int chunk = rep * 256 + tid;
                int row = chunk >> 2;
                int kc  = chunk & 3;
                unsigned dst = smem_u32 +
                    2u * (stage * SM_STAGE + m * SM_MAT + row * SM_ROW + kc * 8);
                const bf16* src = P + (size_t)(base_row + row) * ld + k0 + kc * 8;
                CP16(dst, src);
            }
        }
        asm volatile("cp.async.commit_group;");
    };

    load_stage(0, 0);
    if (nk > 1) load_stage(1, 32);

    for (int kt = 0; kt < nk; kt++) {
        if (kt + 1 < nk) { asm volatile("cp.async.wait_group 1;"); }
        else             { asm volatile("cp.async.wait_group 0;"); }
        __syncthreads();

        unsigned sb  = smem_u32 + (unsigned)(kt % 3) * SM_STAGE_B;
        unsigned aHi = sb + aoffB;
        unsigned aLo = aHi + SM_MAT_B;
        unsigned bHi = sb + 2u * SM_MAT_B + boffB;
        unsigned bLo = bHi + SM_MAT_B;

        #pragma unroll
        for (int kk = 0; kk < 32; kk += 16) {
            uint32_t ah[2][4], al[2][4];
            ldsm4(ah[0], aHi + 2 * kk);
            ldsm4(ah[1], aHi + SM_TILE_B + 2 * kk);
            ldsm4(al[0], aLo + 2 * kk);
            ldsm4(al[1], aLo + SM_TILE_B + 2 * kk);
            uint32_t bh[4][4], bl[4][4];
            #pragma unroll
            for (int p = 0; p < 4; p++) {
                ldsm4(bh[p], bHi + p * SM_TILE_B + 2 * kk);
                ldsm4(bl[p], bLo + p * SM_TILE_B + 2 * kk);
            }
            // term hh: 16 independent MMAs
            #pragma unroll
            for (int p = 0; p < 4; p++)
                #pragma unroll
                for (int mi = 0; mi < 2; mi++) {
                    MMA16816(acc[mi][2 * p],     ah[mi], &bh[p][0]);
                    MMA16816(acc[mi][2 * p + 1], ah[mi], &bh[p][2]);
                }
            // term hl
            #pragma unroll
            for (int p = 0; p < 4; p++)
                #pragma unroll
                for (int mi = 0; mi < 2; mi++) {
                    MMA16816(acc[mi][2 * p],     ah[mi], &bl[p][0]);
                    MMA16816(acc[mi][2 * p + 1], ah[mi], &bl[p][2]);
                }
            // term lh
            #pragma unroll
            for (int p = 0; p < 4; p++)
                #pragma unroll
                for (int mi = 0; mi < 2; mi++) {
                    MMA16816(acc[mi][2 * p],     al[mi], &bh[p][0]);
                    MMA16816(acc[mi][2 * p + 1], al[mi], &bh[p][2]);
                }
        }
        __syncthreads();
        if (kt + 2 < nk) load_stage((kt + 2) % 3, (kt + 2) << 5);
    }

    // ---- epilogue ----
    #pragma unroll
    for (int mi = 0; mi < 2; mi++) {
        int r = row0 + wm * 32 + mi * 16 + g;
        #pragma unroll
        for (int ni = 0; ni < 8; ni++) {
            int c = col0 + wn * 64 + ni * 8 + tg * 2;
            float v0 = acc[mi][ni][0], v1 = acc[mi][ni][1];
            float v2 = acc[mi][ni][2], v3 = acc[mi][ni][3];
            if (bias) {
                float b0 = bias[c], b1 = bias[c + 1];
                v0 += b0; v1 += b1; v2 += b0; v3 += b1;
            }
            if (doRelu) {
                v0 = fmaxf(v0, 0.0f); v1 = fmaxf(v1, 0.0f);
                v2 = fmaxf(v2, 0.0f); v3 = fmaxf(v3, 0.0f);
            }
            if (Chi) {
                float vv[4] = {v0, v1, v2, v3};
                bf16 hh[4], ll[4];
                #pragma unroll
                for (int j = 0; j < 4; j++) {
                    hh[j] = __float2bfloat16(vv[j]);
                    ll[j] = __float2bfloat16(vv[j] - __bfloat162float(hh[j]));
                }
                *(uint32_t*)(Chi + (size_t)r * ldc + c)       = *(uint32_t*)&hh[0];
                *(uint32_t*)(Chi + (size_t)(r + 8) * ldc + c) = *(uint32_t*)&hh[2];
                *(uint32_t*)(Clo + (size_t)r * ldc + c)       = *(uint32_t*)&ll[0];
                *(uint32_t*)(Clo + (size_t)(r + 8) * ldc + c) = *(uint32_t*)&ll[2];
            } else {
                if (res) {
                    v0 += res[(size_t)r * ldc + c];
                    v1 += res[(size_t)r * ldc + c + 1];
                    v2 += res[(size_t)(r + 8) * ldc + c];
                    v3 += res[(size_t)(r + 8) * ldc + c + 1];
                }
                *(float2*)(C + (size_t)r * ldc + c)       = make_float2(v0, v1);
                *(float2*)(C + (size_t)(r + 8) * ldc + c) = make_float2(v2, v3);
            }
        }
    }
}

// ============ attention scores: S = scale * Q @ K^T (2-stage, ldmatrix, term-major) ====
__global__ void __launch_bounds__(256, 1) attn_scores_mma() {
    extern __shared__ bf16 smem[];
    int z = blockIdx.z;
    int qt = blockIdx.y, kt = blockIdx.x;
    if (kt > qt) return;
    int b = z >> 4, h = z & 15;

    const bf16* Ahi = g_qkvhi + (size_t)b * T_ * 3 * E_ + h * HD_;
    const bf16* Alo = g_qkvlo + (size_t)b * T_ * 3 * E_ + h * HD_;
    const bf16* Bhi = g_qkvhi + (size_t)b * T_ * 3 * E_ + E_ + h * HD_;
    const bf16* Blo = g_qkvlo + (size_t)b * T_ * 3 * E_ + E_ + h * HD_;
    const int ld = 3 * E_;
    float* C = g_scores + (size_t)z * T_ * T_;

    int tid  = threadIdx.x;
    int warp = tid >> 5, lane = tid & 31;
    int wm = warp & 3, wn = warp >> 2;
    int g = lane >> 2, tg = lane & 3;
    int t = lane >> 3, rr = lane & 7;
    int row0 = qt * 128, col0 = kt * 128;

    const bf16* planes[4] = {Ahi, Alo, Bhi, Blo};
    unsigned smem_u32 = (unsigned)__cvta_generic_to_shared(smem);
    unsigned aoffB = 2u * ((wm * 32 + (t & 1) * 8 + rr) * SM_ROW + (t >> 1) * 8);
    unsigned boffB = 2u * ((wn * 64 + (t >> 1) * 8 + rr) * SM_ROW + (t & 1) * 8);

    float acc[2][8][4];
    #pragma unroll
    for (int i = 0; i < 2; i++)
        #pragma unroll
        for (int j = 0; j < 8; j++)
            #pragma unroll
            for (int r = 0; r < 4; r++) acc[i][j][r] = 0.0f;

    auto load_stage = [&](int stage, int k0) {
        #pragma unroll
        for (int m = 0; m < 4; m++) {
            const bf16* P = planes[m];
            int base_row = (m < 2) ? row0 : col0;
            #pragma unroll
            for (int rep = 0; rep < 2; rep++) {
                int chunk = rep * 256 + tid;
                int row = chunk >> 2;
                int kc  = chunk & 3;
                unsigned dst = smem_u32 +
                    2u * (stage * SM_STAGE + m * SM_MAT + row * SM_ROW + kc * 8);
                CP16(dst, P + (size_t)(base_row + row) * ld + k0 + kc * 8);
            }
        }
        asm volatile("cp.async.commit_group;");
    };

    load_stage(0, 0);

    #pragma unroll
    for (int kt2 = 0; kt2 < 2; kt2++) {
        if (kt2 == 0) {
            load_stage(1, 32);
            asm volatile("cp.async.wait_group 1;");
        } else {
            asm volatile("cp.async.wait_group 0;");
        }
        __syncthreads();

        unsigned sb  = smem_u32 + (unsigned)kt2 * SM_STAGE_B;
        unsigned aHi = sb + aoffB;
        unsigned aLo = aHi + SM_MAT_B;
        unsigned bHi = sb + 2u * SM_MAT_B + boffB;
        unsigned bLo = bHi + SM_MAT_B;

        #pragma unroll
        for (int kk = 0; kk < 32; kk += 16) {
            uint32_t ah[2][4], al[2][4];
            ldsm4(ah[0], aHi + 2 * kk);
            ldsm4(ah[1], aHi + SM_TILE_B + 2 * kk);
            ldsm4(al[0], aLo + 2 * kk);
            ldsm4(al[1], aLo + SM_TILE_B + 2 * kk);
            uint32_t bh[4][4], bl[4][4];
            #pragma unroll
            for (int p = 0; p < 4; p++) {
                ldsm4(bh[p], bHi + p * SM_TILE_B + 2 * kk);
                ldsm4(bl[p], bLo + p * SM_TILE_B + 2 * kk);
            }
            #pragma unroll
            for (int p = 0; p < 4; p++)
                #pragma unroll
                for (int mi = 0; mi < 2; mi++) {
                    MMA16816(acc[mi][2 * p],     ah[mi], &bh[p][0]);
                    MMA16816(acc[mi][2 * p + 1], ah[mi], &bh[p][2]);
                }
            #pragma unroll
            for (int p = 0; p < 4; p++)
                #pragma unroll
                for (int mi = 0; mi < 2; mi++) {
                    MMA16816(acc[mi][2 * p],     ah[mi], &bl[p][0]);
                    MMA16816(acc[mi][2 * p + 1], ah[mi], &bl[p][2]);
                }
            #pragma unroll
            for (int p = 0; p < 4; p++)
                #pragma unroll
                for (int mi = 0; mi < 2; mi++) {
                    MMA16816(acc[mi][2 * p],     al[mi], &bh[p][0]);
                    MMA16816(acc[mi][2 * p + 1], al[mi], &bh[p][2]);
                }
        }
        __syncthreads();
    }

    #pragma unroll
    for (int mi = 0; mi < 2; mi++) {
        int r = row0 + wm * 32 + mi * 16 + g;
        #pragma unroll
        for (int ni = 0; ni < 8; ni++) {
            int c = col0 + wn * 64 + ni * 8 + tg * 2;
            *(float2*)(C + (size_t)r * T_ + c) =
                make_float2(acc[mi][ni][0] * SCALE_, acc[mi][ni][1] * SCALE_);
            *(float2*)(C + (size_t)(r + 8) * T_ + c) =
                make_float2(acc[mi][ni][2] * SCALE_, acc[mi][ni][3] * SCALE_);
        }
    }
}

// ---------------- causal row softmax -> split bf16 P planes ----------------
__global__ void softmax_split_kernel() {
    int idx = blockIdx.x;
    int q = idx & (T_ - 1);
    const float* row = g_scores + (size_t)idx * T_;
    bf16* ph = g_phi + (size_t)idx * T_;
    bf16* pl = g_plo + (size_t)idx * T_;
    int n = q + 1;
    int kmax = ((q >> 7) + 1) << 7;   // AV only reads up to end of diagonal tile
    int tid = threadIdx.x;
    float m = -1e30f;
    for (int i = tid; i < n; i += 256) m = fmaxf(m, row[i]);
    m = blockMax256(m);
    __syncthreads();
    float s = 0.0f;
    for (int i = tid; i < n; i += 256) s += __expf(row[i] - m);
    s = blockSum256(s);
    float inv = 1.0f / s;
    for (int i = tid; i < n; i += 256) {
        float p = __expf(row[i] - m) * inv;
        bf16 h = __float2bfloat16(p);
        ph[i] = h;
        pl[i] = __float2bfloat16(p - __bfloat162float(h));
    }
    bf16 z16 = __float2bfloat16(0.0f);
    for (int i = n + tid; i < kmax; i += 256) { ph[i] = z16; pl[i] = z16; }
}

// ============ AV: O = P @ V, 128x64 tile, causal K bound, ldmatrix, term-major =====
#define AV_A_PLANE 5120
#define AV_B_PLANE 2560
#define AV_STAGE   15360
#define AV_STAGE_B 30720u

__global__ void __launch_bounds__(256, 1) attn_av_mma() {
    extern __shared__ bf16 smem[];
    int z = blockIdx.z;
    int qt = blockIdx.y;
    int b = z >> 4, h = z & 15;
    int row0 = qt * 128;

    const bf16* Ahi = g_phi + (size_t)z * T_ * T_;
    const bf16* Alo = g_plo + (size_t)z * T_ * T_;
    const bf16* Bhi = g_vthi + (size_t)z * HD_ * T_;
    const bf16* Blo = g_vtlo + (size_t)z * HD_ * T_;

    int tid  = threadIdx.x;
    int warp = tid >> 5, lane = tid & 31;
    int g = lane >> 2, tg = lane & 3;
    int t = lane >> 3, rr = lane & 7;
    unsigned smem_u32 = (unsigned)__cvta_generic_to_shared(smem);
    unsigned aoffB = 2u * ((warp * 16 + (t & 1) * 8 + rr) * SM_ROW + (t >> 1) * 8);
    unsigned boffB = 2u * (((t >> 1) * 8 + rr) * SM_ROW + (t & 1) * 8);

    float acc[8][4];
    #pragma unroll
    for (int j = 0; j < 8; j++)
        #pragma unroll
        for (int r = 0; r < 4; r++) acc[j][r] = 0.0f;

    int nk = (qt + 1) * 4;

    auto load_stage = [&](int stage, int k0) {
        #pragma unroll
        for (int rep = 0; rep < 4; rep++) {
            int chunk = rep * 256 + tid;
            int plane = chunk >> 9;
            int idx = chunk & 511;
            int row = idx >> 2;
            int kc  = idx & 3;
            unsigned dst = smem_u32 +
                2u * (stage * AV_STAGE + plane * AV_A_PLANE + row * SM_ROW + kc * 8);
            const bf16* P = plane ? Alo : Ahi;
            CP16(dst, P + (size_t)(row0 + row) * T_ + k0 + kc * 8);
        }
        #pragma unroll
        for (int rep = 0; rep < 2; rep++) {
            int chunk = rep * 256 + tid;
            int plane = chunk >> 8;
            int idx = chunk & 255;
            int row = idx >> 2;
            int kc  = idx & 3;
            unsigned dst = smem_u32 +
                2u * (stage * AV_STAGE + 2 * AV_A_PLANE + plane * AV_B_PLANE + row * SM_ROW + kc * 8);
            const bf16* P = plane ? Blo : Bhi;
            CP16(dst, P + (size_t)row * T_ + k0 + kc * 8);
        }
        asm volatile("cp.async.commit_group;");
    };

    load_stage(0, 0);

    for (int kt = 0; kt < nk; kt++) {
        if (kt + 1 < nk) {
            load_stage((kt + 1) & 1, (kt + 1) << 5);
            asm volatile("cp.async.wait_group 1;");
        } else {
            asm volatile("cp.async.wait_group 0;");
        }
        __syncthreads();

        unsigned sb  = smem_u32 + (unsigned)(kt & 1) * AV_STAGE_B;
        unsigned aHi = sb + aoffB;
        unsigned aLo = aHi + 2u * AV_A_PLANE;
        unsigned bHi = sb + 4u * AV_A_PLANE + boffB;
        unsigned bLo = bHi + 2u * AV_B_PLANE;

        #pragma unroll
        for (int kk = 0; kk < 32; kk += 16) {
            uint32_t ah[4], al[4];
            ldsm4(ah, aHi + 2 * kk);
            ldsm4(al, aLo + 2 * kk);
            uint32_t bh[4][4], bl[4][4];
            #pragma unroll
            for (int p = 0; p < 4; p++) {
                ldsm4(bh[p], bHi + p * SM_TILE_B + 2 * kk);
                ldsm4(bl[p], bLo + p * SM_TILE_B + 2 * kk);
            }
            #pragma unroll
            for (int p = 0; p < 4; p++) {
                MMA16816(acc[2 * p],     ah, &bh[p][0]);
                MMA16816(acc[2 * p + 1], ah, &bh[p][2]);
            }
            #pragma unroll
            for (int p = 0; p < 4; p++) {
                MMA16816(acc[2 * p],     ah, &bl[p][0]);
                MMA16816(acc[2 * p + 1], ah, &bl[p][2]);
            }
            #pragma unroll
            for (int p = 0; p < 4; p++) {
                MMA16816(acc[2 * p],     al, &bh[p][0]);
                MMA16816(acc[2 * p + 1], al, &bh[p][2]);
            }
        }
        __syncthreads();
    }

    int r = b * T_ + row0 + warp * 16 + g;
    #pragma unroll
    for (int ni = 0; ni < 8; ni++) {
        int c = h * HD_ + ni * 8 + tg * 2;
        float vv[4] = {acc[ni][0], acc[ni][1], acc[ni][2], acc[ni][3]};
        bf16 hh[4], ll[4];
        #pragma unroll
        for (int j = 0; j < 4; j++) {
            hh[j] = __float2bfloat16(vv[j]);
            ll[j] = __float2bfloat16(vv[j] - __bfloat162float(hh[j]));
        }
        *(uint32_t*)(g_ohi + (size_t)r * E_ + c)       = *(uint32_t*)&hh[0];
        *(uint32_t*)(g_ohi + (size_t)(r + 8) * E_ + c) = *(uint32_t*)&hh[2];
        *(uint32_t*)(g_olo + (size_t)r * E_ + c)       = *(uint32_t*)&ll[0];
        *(uint32_t*)(g_olo + (size_t)(r + 8) * E_ + c) = *(uint32_t*)&ll[2];
    }
}

// ---------------- loss ----------------
__global__ void rowloss_kernel(const float* __restrict__ logits, const int* __restrict__ tgt) {
    int row = blockIdx.x;
    const float* lr = logits + (size_t)row * V_;
    int tid = threadIdx.x;
    float m = -1e30f;
    for (int i = tid; i < V_; i += 256) m = fmaxf(m, lr[i]);
    m = blockMax256(m);
    __syncthreads();
    float s = 0.0f;
    for (int i = tid; i < V_; i += 256) s += __expf(lr[i] - m);
    s = blockSum256(s);
    if (tid == 0)
        g_rowloss[row] = -(lr[tgt[row]] - m - logf(s));
}

__global__ void loss_final_kernel(float* __restrict__ dst) {
    int tid = threadIdx.x;
    float s = 0.0f;
    for (int i = tid; i < BT_; i += 256) s += g_rowloss[i];
    s = blockSum256(s);
    if (tid == 0) dst[0] = s * (1.0f / BT_);
}

// ---------------- host driver ----------------
#define GEMM_SMEM 122880
#define SC_SMEM   81920
#define AV_SMEM   61440

extern "C" void kernel_launch(void* const* d_in, const int* in_sizes, int n_in,
                              void* d_out, int out_size) {
    const int*   context = (const int*)  d_in[0];
    const int*   targets = (const int*)  d_in[1];
    const float* tok_emb = (const float*)d_in[2];
    const float* pos_emb = (const float*)d_in[3];
    const float* Wq    = (const float*)d_in[4];
    const float* Wk    = (const float*)d_in[5];
    const float* Wv    = (const float*)d_in[6];
    const float* Wo    = (const float*)d_in[7];
    const float* bo    = (const float*)d_in[8];
    const float* ln1_g = (const float*)d_in[9];
    const float* ln1_b = (const float*)d_in[10];
    const float* ln2_g = (const float*)d_in[11];
    const float* ln2_b = (const float*)d_in[12];
    const float* W1    = (const float*)d_in[13];
    const float* b1    = (const float*)d_in[14];
    const float* W2    = (const float*)d_in[15];
    const float* b2    = (const float*)d_in[16];
    const float* lnf_g = (const float*)d_in[17];
    const float* lnf_b = (const float*)d_in[18];
    const float* Wlm   = (const float*)d_in[19];
    const float* blm   = (const float*)d_in[20];

    float *x, *logits_sym, *lossdummy;
    bf16 *hhi, *hlo, *qkvhi, *qkvlo, *ffhi, *fflo, *ohi, *olo, *wthi, *wtlo;
    cudaGetSymbolAddress((void**)&x,   g_x);
    cudaGetSymbolAddress((void**)&logits_sym, g_logits);
    cudaGetSymbolAddress((void**)&lossdummy,  g_lossdummy);
    cudaGetSymbolAddress((void**)&hhi, g_hhi);
    cudaGetSymbolAddress((void**)&hlo, g_hlo);
    cudaGetSymbolAddress((void**)&qkvhi, g_qkvhi);
    cudaGetSymbolAddress((void**)&qkvlo, g_qkvlo);
    cudaGetSymbolAddress((void**)&ffhi, g_ffhi);
    cudaGetSymbolAddress((void**)&fflo, g_fflo);
    cudaGetSymbolAddress((void**)&ohi, g_ohi);
    cudaGetSymbolAddress((void**)&olo, g_olo);
    cudaGetSymbolAddress((void**)&wthi, g_wthi);
    cudaGetSymbolAddress((void**)&wtlo, g_wtlo);

    cudaFuncSetAttribute(mma_gemm, cudaFuncAttributeMaxDynamicSharedMemorySize, GEMM_SMEM);
    cudaFuncSetAttribute(attn_scores_mma, cudaFuncAttributeMaxDynamicSharedMemorySize, SC_SMEM);
    cudaFuncSetAttribute(attn_av_mma, cudaFuncAttributeMaxDynamicSharedMemorySize, AV_SMEM);

    const long long BTV = (long long)BT_ * V_;
    float* out = (float*)d_out;
    float* logits = ((long long)out_size >= BTV) ? out : logits_sym;
    float* lossdst;
    if ((long long)out_size > BTV)       lossdst = out + BTV;
    else if ((long long)out_size < BTV)  lossdst = out;
    else                                 lossdst = lossdummy;

    embed_kernel<<<(BT_ * E_) / 256, 256>>>(context, tok_emb, pos_emb);

    dim3 gQKV(3 * E_ / 128, BT_ / 128);
    dim3 gE(E_ / 128, BT_ / 128);
    dim3 gFF(FF_ / 128, BT_ / 128);
    dim3 gV2(V_ / 128, BT_ / 128);
    dim3 gSc(T_ / 128, T_ / 128, B_ * H_);
    dim3 gAV(1, T_ / 128, B_ * H_);
    dim3 gVT(T_ / 32, HD_ / 32, B_ * H_);
    dim3 tT(8, 32);
    dim3 tVT(32, 32);

    for (int l = 0; l < L_; l++) {
        const float* wq = Wq + (size_t)l * E_ * E_;
        const float* wk = Wk + (size_t)l * E_ * E_;
        const float* wv = Wv + (size_t)l * E_ * E_;
        const float* wo = Wo + (size_t)l * E_ * E_;
        const float* w1 = W1 + (size_t)l * E_ * FF_;
        const float* w2 = W2 + (size_t)l * FF_ * E_;

        // ---- attention block ----
        ln_split_kernel<<<BT_, 256>>>(x, hhi, hlo, ln1_g + l * E_, ln1_b + l * E_);
        wt_tsplit<<<dim3(E_ / 32, E_ / 32), tT>>>(wq, wthi,                       wtlo,                       E_, E_);
        wt_tsplit<<<dim3(E_ / 32, E_ / 32), tT>>>(wk, wthi + (size_t)E_ * E_,     wtlo + (size_t)E_ * E_,     E_, E_);
        wt_tsplit<<<dim3(E_ / 32, E_ / 32), tT>>>(wv, wthi + (size_t)2 * E_ * E_, wtlo + (size_t)2 * E_ * E_, E_, E_);
        mma_gemm<<<gQKV, 256, GEMM_SMEM>>>(hhi, hlo, E_, wthi, wtlo, E_,
                                           nullptr, nullptr, nullptr, qkvhi, qkvlo,
                                           3 * E_, E_, 0);
        vt_tsplit_kernel<<<gVT, tVT>>>();
        attn_scores_mma<<<gSc, 256, SC_SMEM>>>();
        softmax_split_kernel<<<B_ * H_ * T_, 256>>>();
        attn_av_mma<<<gAV, 256, AV_SMEM>>>();
        wt_tsplit<<<dim3(E_ / 32, E_ / 32), tT>>>(wo, wthi, wtlo, E_, E_);
        mma_gemm<<<gE, 256, GEMM_SMEM>>>(ohi, olo, E_, wthi, wtlo, E_,
                                         bo + l * E_, x, x, nullptr, nullptr,
                                         E_, E_, 0);

        // ---- MLP block ----
        ln_split_kernel<<<BT_, 256>>>(x, hhi, hlo, ln2_g + l * E_, ln2_b + l * E_);
        wt_tsplit<<<dim3(FF_ / 32, E_ / 32), tT>>>(w1, wthi, wtlo, FF_, E_);
        mma_gemm<<<gFF, 256, GEMM_SMEM>>>(hhi, hlo, E_, wthi, wtlo, E_,
                                          b1 + l * FF_, nullptr, nullptr, ffhi, fflo,
                                          FF_, E_, 1);
        wt_tsplit<<<dim3(E_ / 32, FF_ / 32), tT>>>(w2, wthi, wtlo, E_, FF_);
        mma_gemm<<<gE, 256, GEMM_SMEM>>>(ffhi, fflo, FF_, wthi, wtlo, FF_,
                                         b2 + l * E_, x, x, nullptr, nullptr,
                                         E_, FF_, 0);
    }

    // ---- final LN + LM head ----
    ln_split_kernel<<<BT_, 256>>>(x, hhi, hlo, lnf_g, lnf_b);
    wt_tsplit<<<dim3(V_ / 32, E_ / 32), tT>>>(Wlm, wthi, wtlo, V_, E_);
    mma_gemm<<<gV2, 256, GEMM_SMEM>>>(hhi, hlo, E_, wthi, wtlo, E_,
                                      blm, nullptr, logits, nullptr, nullptr,
                                      V_, E_, 0);

    rowloss_kernel<<<BT_, 256>>>(logits, targets);
    loss_final_kernel<<<1, 256>>>(lossdst);
}